// round 9
// baseline (speedup 1.0000x reference)
#include <cuda_runtime.h>
#include <cuda_fp16.h>
#include <math.h>
#include <stdint.h>

#define NN 100000
#define DD 128
#define NE 1600000

#define MLP_THREADS 128          // 4 warps; each warp owns 32 rows
#define ROWS_PER_BLOCK 128
#define N_CHUNKS 24              // 12 layer-0 (384 k) + 12 inner (3 x 128 k)
#define HS16 68                  // H slab row stride in uint32 (half2) units

// Scratch (allocation-free rule: __device__ globals)
// Column layout of all fp16 node matrices is PERMUTED: within each group of
// 8 half2-words, logical words (0..7) are stored in order (0,4,1,5,2,6,3,7),
// so the MMA A-fragment pair (t4, t4+4) is one aligned 8-byte load.
__device__ uint32_t g_xh[(size_t)NN * 64];
__device__ uint32_t g_mih[(size_t)NN * 64];
__device__ uint32_t g_moh[(size_t)NN * 64];

__device__ int   g_cnt[2 * NN + 2];   // [2NN..2NN+2): global cursors
__device__ int   g_off_in[NN];
__device__ int   g_off_out[NN];
__device__ int   g_cur_in[NN];
__device__ int   g_cur_out[NN];
__device__ int2  g_lst_in[NE];
__device__ int2  g_lst_out[NE];
__device__ uint4 g_wfrag[N_CHUNKS * 2 * 8 * 32];   // fp16 frag-major weights

// ---------------------------------------------------------------------------
__device__ __forceinline__ float fast_tanh(float x) {
    float ax = fabsf(x);
    float t = __expf(-2.f * ax);
    float r = (1.f - t) * __frcp_rn(1.f + t);
    return copysignf(r, x);
}

__device__ __forceinline__ uint32_t pack_h2(float a, float b) {
    __half2 h = __floats2half2_rn(a, b);
    return *(uint32_t*)&h;
}

// ---------------------------------------------------------------------------
// x fp32 -> permuted fp16 layout. Thread handles one 8-word group (16 halfs).
// Stored group order: logical words (0,4,1,5,2,6,3,7).
// ---------------------------------------------------------------------------
__global__ void xconv_kernel(const float* __restrict__ x, uint32_t* __restrict__ xh) {
    int i = blockIdx.x * blockDim.x + threadIdx.x;
    if (i >= NN * 8) return;
    int node = i >> 3;
    int gi = i & 7;
    const float4* xr = (const float4*)(x + (size_t)node * DD + gi * 16);
    float4 q0 = __ldg(xr + 0);
    float4 q1 = __ldg(xr + 1);
    float4 q2 = __ldg(xr + 2);
    float4 q3 = __ldg(xr + 3);
    uint4 o0, o1;
    o0.x = pack_h2(q0.x, q0.y);   // w0
    o0.y = pack_h2(q2.x, q2.y);   // w4
    o0.z = pack_h2(q0.z, q0.w);   // w1
    o0.w = pack_h2(q2.z, q2.w);   // w5
    o1.x = pack_h2(q1.x, q1.y);   // w2
    o1.y = pack_h2(q3.x, q3.y);   // w6
    o1.z = pack_h2(q1.z, q1.w);   // w3
    o1.w = pack_h2(q3.z, q3.w);   // w7
    uint4* dst = (uint4*)(xh + (size_t)node * 64 + gi * 8);
    dst[0] = o0;
    dst[1] = o1;
}

// ---------------------------------------------------------------------------
// W0 [384,128] + W [3,128,128] -> fp16 fragment-major for m16n8k16.
// ---------------------------------------------------------------------------
__global__ void wfrag_kernel(const float* __restrict__ W0,
                             const float* __restrict__ W,
                             uint4* __restrict__ WF) {
    int idx = blockIdx.x * blockDim.x + threadIdx.x;
    if (idx >= N_CHUNKS * 2 * 8 * 32) return;
    int lane = idx & 31;
    int q = (idx >> 5) & 7;
    int s = (idx >> 8) & 1;
    int chunk = idx >> 9;
    int t4 = lane & 3, g = lane >> 2;

    const float* Wsrc;
    int kbase;
    if (chunk < 12) {
        Wsrc = W0;
        kbase = chunk * 32;
    } else {
        int c2 = chunk - 12;
        Wsrc = W + (size_t)(c2 >> 2) * 128 * 128;
        kbase = (c2 & 3) * 32;
    }
    int k0 = kbase + s * 16 + 2 * t4;
    int n0 = (2 * q) * 8 + g;
    int n1 = n0 + 8;

    uint4 o;
    o.x = pack_h2(__ldg(&Wsrc[(size_t)k0 * 128 + n0]),       __ldg(&Wsrc[(size_t)(k0 + 1) * 128 + n0]));
    o.y = pack_h2(__ldg(&Wsrc[(size_t)(k0 + 8) * 128 + n0]), __ldg(&Wsrc[(size_t)(k0 + 9) * 128 + n0]));
    o.z = pack_h2(__ldg(&Wsrc[(size_t)k0 * 128 + n1]),       __ldg(&Wsrc[(size_t)(k0 + 1) * 128 + n1]));
    o.w = pack_h2(__ldg(&Wsrc[(size_t)(k0 + 8) * 128 + n1]), __ldg(&Wsrc[(size_t)(k0 + 9) * 128 + n1]));
    WF[idx] = o;
}

// ---------------------------------------------------------------------------
// Histogram (8 edges/thread)
// ---------------------------------------------------------------------------
__global__ void hist_kernel(const int* __restrict__ ei, int* __restrict__ cnt) {
    int i = blockIdx.x * blockDim.x + threadIdx.x;
    if (i >= NE / 8) return;
    int4 s0 = __ldg((const int4*)ei + 2 * i);
    int4 s1 = __ldg((const int4*)ei + 2 * i + 1);
    int4 t0 = __ldg((const int4*)(ei + NE) + 2 * i);
    int4 t1 = __ldg((const int4*)(ei + NE) + 2 * i + 1);
    atomicAdd(&cnt[t0.x], 1); atomicAdd(&cnt[t0.y], 1);
    atomicAdd(&cnt[t0.z], 1); atomicAdd(&cnt[t0.w], 1);
    atomicAdd(&cnt[t1.x], 1); atomicAdd(&cnt[t1.y], 1);
    atomicAdd(&cnt[t1.z], 1); atomicAdd(&cnt[t1.w], 1);
    atomicAdd(&cnt[NN + s0.x], 1); atomicAdd(&cnt[NN + s0.y], 1);
    atomicAdd(&cnt[NN + s0.z], 1); atomicAdd(&cnt[NN + s0.w], 1);
    atomicAdd(&cnt[NN + s1.x], 1); atomicAdd(&cnt[NN + s1.y], 1);
    atomicAdd(&cnt[NN + s1.z], 1); atomicAdd(&cnt[NN + s1.w], 1);
}

// ---------------------------------------------------------------------------
// Parallel segment allocation (offsets unordered)
// ---------------------------------------------------------------------------
__global__ void alloc_kernel(const int* __restrict__ cnt,
                             int* __restrict__ offin, int* __restrict__ curin,
                             int* __restrict__ offout, int* __restrict__ curout,
                             int* __restrict__ cursors) {
    int i = blockIdx.x * blockDim.x + threadIdx.x;
    if (i >= 2 * NN) return;
    int lane = threadIdx.x & 31;
    int c = cnt[i];
    int inc = c;
#pragma unroll
    for (int o = 1; o < 32; o <<= 1) {
        int v = __shfl_up_sync(0xFFFFFFFFu, inc, o);
        if (lane >= o) inc += v;
    }
    int tot = __shfl_sync(0xFFFFFFFFu, inc, 31);
    int ex = inc - c;
    int half = (i < NN) ? 0 : 1;
    int base = 0;
    if (lane == 0) base = atomicAdd(&cursors[half], tot);
    base = __shfl_sync(0xFFFFFFFFu, base, 0);
    int off = base + ex;
    if (half == 0) { offin[i] = off; curin[i] = off; }
    else           { offout[i - NN] = off; curout[i - NN] = off; }
}

// ---------------------------------------------------------------------------
// Fill CSR lists (8 edges/thread, atomics batched before stores)
// ---------------------------------------------------------------------------
__global__ void fill_kernel(const int* __restrict__ ei, const float* __restrict__ e,
                            int* __restrict__ curin, int* __restrict__ curout,
                            int2* __restrict__ lin, int2* __restrict__ lout) {
    int i = blockIdx.x * blockDim.x + threadIdx.x;
    if (i >= NE / 8) return;
    int4 s0 = __ldg((const int4*)ei + 2 * i);
    int4 s1 = __ldg((const int4*)ei + 2 * i + 1);
    int4 t0 = __ldg((const int4*)(ei + NE) + 2 * i);
    int4 t1 = __ldg((const int4*)(ei + NE) + 2 * i + 1);
    float4 w0 = __ldg((const float4*)e + 2 * i);
    float4 w1 = __ldg((const float4*)e + 2 * i + 1);
    int ss[8] = {s0.x, s0.y, s0.z, s0.w, s1.x, s1.y, s1.z, s1.w};
    int tt[8] = {t0.x, t0.y, t0.z, t0.w, t1.x, t1.y, t1.z, t1.w};
    float ww[8] = {w0.x, w0.y, w0.z, w0.w, w1.x, w1.y, w1.z, w1.w};

    int pin[8], pout[8];
#pragma unroll
    for (int u = 0; u < 8; u++) pin[u] = atomicAdd(&curin[tt[u]], 1);
#pragma unroll
    for (int u = 0; u < 8; u++) pout[u] = atomicAdd(&curout[ss[u]], 1);
#pragma unroll
    for (int u = 0; u < 8; u++) lin[pin[u]] = make_int2(ss[u], __float_as_int(ww[u]));
#pragma unroll
    for (int u = 0; u < 8; u++) lout[pout[u]] = make_int2(tt[u], __float_as_int(ww[u]));
}

// ---------------------------------------------------------------------------
// Gather (fp16): one warp per (node, dir). Permutation-transparent: reads and
// writes the same stored word positions with uniform scalar weights.
// ---------------------------------------------------------------------------
__global__ __launch_bounds__(256) void gather_kernel(
    const uint32_t* __restrict__ xh, const int* __restrict__ cnt,
    const int* __restrict__ offin, const int2* __restrict__ lin,
    const int* __restrict__ offout, const int2* __restrict__ lout,
    uint32_t* __restrict__ mih, uint32_t* __restrict__ moh) {
    int wg = (blockIdx.x * blockDim.x + threadIdx.x) >> 5;
    int lane = threadIdx.x & 31;
    if (wg >= 2 * NN) return;

    const int* off;
    const int2* lst;
    uint32_t* dst;
    int node, cofs;
    if (wg < NN) { node = wg; off = offin; lst = lin; dst = mih; cofs = 0; }
    else         { node = wg - NN; off = offout; lst = lout; dst = moh; cofs = NN; }

    int beg = off[node];
    int end = beg + cnt[cofs + node];

    float2 acc0 = make_float2(0.f, 0.f);
    float2 acc1 = make_float2(0.f, 0.f);

    int j = beg;
    for (; j + 8 <= end; j += 8) {
        int2 p[8];
#pragma unroll
        for (int u = 0; u < 8; u++) p[u] = __ldg(&lst[j + u]);
        uint2 v[8];
#pragma unroll
        for (int u = 0; u < 8; u++)
            v[u] = __ldg((const uint2*)(xh + (size_t)p[u].x * 64) + lane);
#pragma unroll
        for (int u = 0; u < 8; u++) {
            float w = __int_as_float(p[u].y);
            float2 f0 = __half22float2(*(__half2*)&v[u].x);
            float2 f1 = __half22float2(*(__half2*)&v[u].y);
            acc0.x = fmaf(w, f0.x, acc0.x); acc0.y = fmaf(w, f0.y, acc0.y);
            acc1.x = fmaf(w, f1.x, acc1.x); acc1.y = fmaf(w, f1.y, acc1.y);
        }
    }
    for (; j < end; j++) {
        int2 p0 = __ldg(&lst[j]);
        uint2 v0 = __ldg((const uint2*)(xh + (size_t)p0.x * 64) + lane);
        float w = __int_as_float(p0.y);
        float2 f0 = __half22float2(*(__half2*)&v0.x);
        float2 f1 = __half22float2(*(__half2*)&v0.y);
        acc0.x = fmaf(w, f0.x, acc0.x); acc0.y = fmaf(w, f0.y, acc0.y);
        acc1.x = fmaf(w, f1.x, acc1.x); acc1.y = fmaf(w, f1.y, acc1.y);
    }

    uint2 o;
    o.x = pack_h2(acc0.x, acc0.y);
    o.y = pack_h2(acc1.x, acc1.y);
    ((uint2*)(dst + (size_t)node * 64))[lane] = o;
}

// ---------------------------------------------------------------------------
// Fused 4-layer MLP, fp16 m16n8k16. A-fragment pairs are single 8B loads
// thanks to the permuted layout. 3 blocks/SM for latency hiding.
// ---------------------------------------------------------------------------
#define MMA16(cj, A0r, A1r, A2r, A3r, B0r, B1r)                                  \
    asm volatile(                                                                \
        "mma.sync.aligned.m16n8k16.row.col.f32.f16.f16.f32 "                     \
        "{%0,%1,%2,%3}, {%4,%5,%6,%7}, {%8,%9}, {%0,%1,%2,%3};"                  \
        : "+f"(cj[0]), "+f"(cj[1]), "+f"(cj[2]), "+f"(cj[3])                     \
        : "r"(A0r), "r"(A1r), "r"(A2r), "r"(A3r), "r"(B0r), "r"(B1r))

__global__ __launch_bounds__(MLP_THREADS, 3) void mlp_fused(
    const uint32_t* __restrict__ A0h, const uint32_t* __restrict__ A1h,
    const uint32_t* __restrict__ A2h,
    const uint4* __restrict__ WF,
    const float* __restrict__ b0v, const float* __restrict__ g0v,
    const float* __restrict__ be0v,
    const float* __restrict__ bv, const float* __restrict__ gv,
    const float* __restrict__ bev,
    float* __restrict__ out)
{
    extern __shared__ uint32_t smem[];
    const int tid = threadIdx.x;
    const int lane = tid & 31;
    const int wid = tid >> 5;
    const int g = lane >> 2;
    const int t4 = lane & 3;
    const int row0 = blockIdx.x * ROWS_PER_BLOCK + wid * 32;

    uint32_t* Hw = smem + wid * 32 * HS16;   // per-warp slab [32][HS16] half2

    float c[2][16][4];
#pragma unroll
    for (int t = 0; t < 2; t++)
#pragma unroll
        for (int j = 0; j < 16; j++)
#pragma unroll
            for (int q = 0; q < 4; q++) c[t][j][q] = 0.f;

    int r00 = row0 + g;
    int r10 = row0 + 16 + g;
    size_t cr00 = (size_t)(r00 < NN ? r00 : 0) * 64;
    size_t cr01 = (size_t)((r00 + 8) < NN ? (r00 + 8) : 0) * 64;
    size_t cr10 = (size_t)(r10 < NN ? r10 : 0) * 64;
    size_t cr11 = (size_t)((r10 + 8) < NN ? (r10 + 8) : 0) * 64;

    // ---------------- Layer 0: K = 384 over {mih, moh, xh} ----------------
    const uint32_t* Ap[3] = {A0h, A1h, A2h};
#pragma unroll 1
    for (int m = 0; m < 3; m++) {
        const uint32_t* A = Ap[m];
#pragma unroll
        for (int kc = 0; kc < 4; kc++) {
            int chunk = m * 4 + kc;
#pragma unroll
            for (int s = 0; s < 2; s++) {
                int group8 = (kc * 2 + s) * 8;
                uint32_t a0[4], a1[4];
                uint2 v;
                v = __ldg((const uint2*)(A + cr00 + group8) + t4); a0[0] = v.x; a0[2] = v.y;
                v = __ldg((const uint2*)(A + cr01 + group8) + t4); a0[1] = v.x; a0[3] = v.y;
                v = __ldg((const uint2*)(A + cr10 + group8) + t4); a1[0] = v.x; a1[2] = v.y;
                v = __ldg((const uint2*)(A + cr11 + group8) + t4); a1[1] = v.x; a1[3] = v.y;
                const uint4* wfk = WF + ((size_t)(chunk * 2 + s) << 8);
#pragma unroll
                for (int q = 0; q < 8; q++) {
                    uint4 bb = __ldg(&wfk[(q << 5) + lane]);
                    MMA16(c[0][2 * q],     a0[0], a0[1], a0[2], a0[3], bb.x, bb.y);
                    MMA16(c[0][2 * q + 1], a0[0], a0[1], a0[2], a0[3], bb.z, bb.w);
                    MMA16(c[1][2 * q],     a1[0], a1[1], a1[2], a1[3], bb.x, bb.y);
                    MMA16(c[1][2 * q + 1], a1[0], a1[1], a1[2], a1[3], bb.z, bb.w);
                }
            }
        }
    }

    // ---------------- 4 epilogues + 3 inner layers ----------------
#pragma unroll 1
    for (int l = 0; l < 4; l++) {
        const float* bias  = (l == 0) ? b0v  : bv  + (l - 1) * 128;
        const float* gamma = (l == 0) ? g0v  : gv  + (l - 1) * 128;
        const float* beta  = (l == 0) ? be0v : bev + (l - 1) * 128;

        float s[2][2], qq[2][2];
#pragma unroll
        for (int t = 0; t < 2; t++) { s[t][0]=s[t][1]=qq[t][0]=qq[t][1]=0.f; }

#pragma unroll
        for (int j = 0; j < 16; j++) {
            int col = j * 8 + 2 * t4;
            float2 bb = __ldg((const float2*)(bias + col));
#pragma unroll
            for (int t = 0; t < 2; t++) {
                c[t][j][0] += bb.x; c[t][j][1] += bb.y;
                c[t][j][2] += bb.x; c[t][j][3] += bb.y;
                s[t][0]  += c[t][j][0] + c[t][j][1];
                qq[t][0] += c[t][j][0] * c[t][j][0] + c[t][j][1] * c[t][j][1];
                s[t][1]  += c[t][j][2] + c[t][j][3];
                qq[t][1] += c[t][j][2] * c[t][j][2] + c[t][j][3] * c[t][j][3];
            }
        }
#pragma unroll
        for (int o = 1; o <= 2; o <<= 1) {
#pragma unroll
            for (int t = 0; t < 2; t++) {
                s[t][0]  += __shfl_xor_sync(0xFFFFFFFFu, s[t][0], o);
                qq[t][0] += __shfl_xor_sync(0xFFFFFFFFu, qq[t][0], o);
                s[t][1]  += __shfl_xor_sync(0xFFFFFFFFu, s[t][1], o);
                qq[t][1] += __shfl_xor_sync(0xFFFFFFFFu, qq[t][1], o);
            }
        }
        float mean[2][2], rstd[2][2];
#pragma unroll
        for (int t = 0; t < 2; t++)
#pragma unroll
            for (int h = 0; h < 2; h++) {
                mean[t][h] = s[t][h] * (1.f / 128.f);
                rstd[t][h] = rsqrtf(qq[t][h] * (1.f / 128.f) - mean[t][h] * mean[t][h] + 1e-5f);
            }

        if (l == 3) {
#pragma unroll
            for (int j = 0; j < 16; j++) {
                int col = j * 8 + 2 * t4;
                float2 gg = __ldg((const float2*)(gamma + col));
                float2 ee = __ldg((const float2*)(beta + col));
#pragma unroll
                for (int t = 0; t < 2; t++) {
                    int ra = row0 + t * 16 + g;
                    int rb = ra + 8;
                    if (ra < NN) {
                        float2 o1;
                        o1.x = fast_tanh((c[t][j][0] - mean[t][0]) * rstd[t][0] * gg.x + ee.x);
                        o1.y = fast_tanh((c[t][j][1] - mean[t][0]) * rstd[t][0] * gg.y + ee.y);
                        *(float2*)(out + (size_t)ra * DD + col) = o1;
                    }
                    if (rb < NN) {
                        float2 o2;
                        o2.x = fast_tanh((c[t][j][2] - mean[t][1]) * rstd[t][1] * gg.x + ee.x);
                        o2.y = fast_tanh((c[t][j][3] - mean[t][1]) * rstd[t][1] * gg.y + ee.y);
                        *(float2*)(out + (size_t)rb * DD + col) = o2;
                    }
                }
            }
            break;
        }

        // Write h (half2) into per-warp smem slab in PERMUTED layout:
        // logical word (j*4 + t4) -> stored index (j>>1)*8 + 2*t4 + (j&1).
        __syncwarp();
#pragma unroll
        for (int j = 0; j < 16; j++) {
            int col = j * 8 + 2 * t4;
            float2 gg = __ldg((const float2*)(gamma + col));
            float2 ee = __ldg((const float2*)(beta + col));
            int ci = (j >> 1) * 8 + 2 * t4 + (j & 1);
#pragma unroll
            for (int t = 0; t < 2; t++) {
                float h00 = fast_tanh((c[t][j][0] - mean[t][0]) * rstd[t][0] * gg.x + ee.x);
                float h01 = fast_tanh((c[t][j][1] - mean[t][0]) * rstd[t][0] * gg.y + ee.y);
                float h10 = fast_tanh((c[t][j][2] - mean[t][1]) * rstd[t][1] * gg.x + ee.x);
                float h11 = fast_tanh((c[t][j][3] - mean[t][1]) * rstd[t][1] * gg.y + ee.y);
                Hw[(t * 16 + g) * HS16 + ci]     = pack_h2(h00, h01);
                Hw[(t * 16 + g + 8) * HS16 + ci] = pack_h2(h10, h11);
                c[t][j][0] = 0.f; c[t][j][1] = 0.f;
                c[t][j][2] = 0.f; c[t][j][3] = 0.f;
            }
        }
        __syncwarp();

        // Next layer GEMM: h (in Hw, permuted) @ W[l], K = 128
#pragma unroll
        for (int kc = 0; kc < 4; kc++) {
            int chunk = 12 + l * 4 + kc;
#pragma unroll
            for (int s = 0; s < 2; s++) {
                int group8 = (kc * 2 + s) * 8;
                uint32_t a0[4], a1[4];
                uint2 v;
                v = *(const uint2*)(Hw + (g) * HS16 + group8 + 2 * t4);      a0[0] = v.x; a0[2] = v.y;
                v = *(const uint2*)(Hw + (g + 8) * HS16 + group8 + 2 * t4);  a0[1] = v.x; a0[3] = v.y;
                v = *(const uint2*)(Hw + (16 + g) * HS16 + group8 + 2 * t4); a1[0] = v.x; a1[2] = v.y;
                v = *(const uint2*)(Hw + (24 + g) * HS16 + group8 + 2 * t4); a1[1] = v.x; a1[3] = v.y;
                const uint4* wfk = WF + ((size_t)(chunk * 2 + s) << 8);
#pragma unroll
                for (int q = 0; q < 8; q++) {
                    uint4 bb = __ldg(&wfk[(q << 5) + lane]);
                    MMA16(c[0][2 * q],     a0[0], a0[1], a0[2], a0[3], bb.x, bb.y);
                    MMA16(c[0][2 * q + 1], a0[0], a0[1], a0[2], a0[3], bb.z, bb.w);
                    MMA16(c[1][2 * q],     a1[0], a1[1], a1[2], a1[3], bb.x, bb.y);
                    MMA16(c[1][2 * q + 1], a1[0], a1[1], a1[2], a1[3], bb.z, bb.w);
                }
            }
        }
    }
}

// ---------------------------------------------------------------------------
extern "C" void kernel_launch(void* const* d_in, const int* in_sizes, int n_in,
                              void* d_out, int out_size) {
    const float* x   = (const float*)d_in[0];
    const float* e   = (const float*)d_in[1];
    const int*   ei  = (const int*)d_in[2];
    const float* W0  = (const float*)d_in[3];
    const float* b0  = (const float*)d_in[4];
    const float* g0  = (const float*)d_in[5];
    const float* be0 = (const float*)d_in[6];
    const float* W   = (const float*)d_in[7];
    const float* b   = (const float*)d_in[8];
    const float* g   = (const float*)d_in[9];
    const float* be  = (const float*)d_in[10];
    float* out = (float*)d_out;

    uint32_t *xh, *mih, *moh;
    int *cnt, *offin, *offout, *curin, *curout;
    int2 *lin, *lout;
    uint4* wf;
    cudaGetSymbolAddress((void**)&xh, g_xh);
    cudaGetSymbolAddress((void**)&mih, g_mih);
    cudaGetSymbolAddress((void**)&moh, g_moh);
    cudaGetSymbolAddress((void**)&cnt, g_cnt);
    cudaGetSymbolAddress((void**)&offin, g_off_in);
    cudaGetSymbolAddress((void**)&offout, g_off_out);
    cudaGetSymbolAddress((void**)&curin, g_cur_in);
    cudaGetSymbolAddress((void**)&curout, g_cur_out);
    cudaGetSymbolAddress((void**)&lin, g_lst_in);
    cudaGetSymbolAddress((void**)&lout, g_lst_out);
    cudaGetSymbolAddress((void**)&wf, g_wfrag);
    int* cursors = cnt + 2 * NN;

    const int smem_bytes = 4 * 32 * HS16 * 4;   // 4 warps x 32 rows x 68 words
    cudaFuncSetAttribute(mlp_fused,
                         cudaFuncAttributeMaxDynamicSharedMemorySize,
                         smem_bytes);

    cudaMemsetAsync(cnt, 0, (2 * NN + 2) * sizeof(int));

    xconv_kernel<<<(NN * 8 + 255) / 256, 256>>>(x, xh);
    wfrag_kernel<<<(N_CHUNKS * 512 + 255) / 256, 256>>>(W0, W, wf);
    hist_kernel<<<(NE / 8 + 255) / 256, 256>>>(ei, cnt);
    alloc_kernel<<<(2 * NN + 255) / 256, 256>>>(cnt, offin, curin, offout, curout, cursors);
    fill_kernel<<<(NE / 8 + 255) / 256, 256>>>(ei, e, curin, curout, lin, lout);

    {
        long long warps = 2LL * NN;
        int blocks = (int)((warps * 32 + 255) / 256);
        gather_kernel<<<blocks, 256>>>(xh, cnt, offin, lin, offout, lout, mih, moh);
    }

    const int gblocks = (NN + ROWS_PER_BLOCK - 1) / ROWS_PER_BLOCK;  // 782
    mlp_fused<<<gblocks, MLP_THREADS, smem_bytes>>>(
        mih, moh, xh, wf, b0, g0, be0, b, g, be, out);
}

// round 10
// speedup vs baseline: 1.0499x; 1.0499x over previous
#include <cuda_runtime.h>
#include <cuda_fp16.h>
#include <math.h>
#include <stdint.h>

#define NN 100000
#define DD 128
#define NE 1600000

#define MLP_THREADS 128          // 4 warps; each warp owns 32 rows
#define ROWS_PER_BLOCK 128
#define N_CHUNKS 24              // 12 layer-0 (384 k) + 12 inner (3 x 128 k)
#define HS16 68                  // H slab row stride in uint32 (half2) units

// Scratch (allocation-free rule: __device__ globals)
// Column layout of all fp16 node matrices is PERMUTED: within each group of
// 8 half2-words, logical words (0..7) are stored in order (0,4,1,5,2,6,3,7),
// so the MMA A-fragment pair (t4, t4+4) is one aligned 8-byte load.
__device__ uint32_t g_xh[(size_t)NN * 64];
__device__ uint32_t g_mih[(size_t)NN * 64];
__device__ uint32_t g_moh[(size_t)NN * 64];

__device__ int   g_cnt[2 * NN + 2];   // [2NN..2NN+2): global cursors
__device__ int   g_off_in[NN];
__device__ int   g_off_out[NN];
__device__ int   g_cur_in[NN];
__device__ int   g_cur_out[NN];
__device__ int2  g_lst_in[NE];
__device__ int2  g_lst_out[NE];
__device__ uint4 g_wfrag[N_CHUNKS * 2 * 8 * 32];   // fp16 frag-major weights

// ---------------------------------------------------------------------------
__device__ __forceinline__ float fast_tanh(float x) {
    float ax = fabsf(x);
    float t = __expf(-2.f * ax);
    float r = (1.f - t) * __frcp_rn(1.f + t);
    return copysignf(r, x);
}

__device__ __forceinline__ uint32_t pack_h2(float a, float b) {
    __half2 h = __floats2half2_rn(a, b);
    return *(uint32_t*)&h;
}

// ---------------------------------------------------------------------------
// x fp32 -> permuted fp16 layout. Thread handles one 8-word group (16 halfs).
// Stored group order: logical words (0,4,1,5,2,6,3,7).
// ---------------------------------------------------------------------------
__global__ void xconv_kernel(const float* __restrict__ x, uint32_t* __restrict__ xh) {
    int i = blockIdx.x * blockDim.x + threadIdx.x;
    if (i >= NN * 8) return;
    int node = i >> 3;
    int gi = i & 7;
    const float4* xr = (const float4*)(x + (size_t)node * DD + gi * 16);
    float4 q0 = __ldg(xr + 0);
    float4 q1 = __ldg(xr + 1);
    float4 q2 = __ldg(xr + 2);
    float4 q3 = __ldg(xr + 3);
    uint4 o0, o1;
    o0.x = pack_h2(q0.x, q0.y);   // w0
    o0.y = pack_h2(q2.x, q2.y);   // w4
    o0.z = pack_h2(q0.z, q0.w);   // w1
    o0.w = pack_h2(q2.z, q2.w);   // w5
    o1.x = pack_h2(q1.x, q1.y);   // w2
    o1.y = pack_h2(q3.x, q3.y);   // w6
    o1.z = pack_h2(q1.z, q1.w);   // w3
    o1.w = pack_h2(q3.z, q3.w);   // w7
    uint4* dst = (uint4*)(xh + (size_t)node * 64 + gi * 8);
    dst[0] = o0;
    dst[1] = o1;
}

// ---------------------------------------------------------------------------
// W0 [384,128] + W [3,128,128] -> fp16 fragment-major for m16n8k16.
// ---------------------------------------------------------------------------
__global__ void wfrag_kernel(const float* __restrict__ W0,
                             const float* __restrict__ W,
                             uint4* __restrict__ WF) {
    int idx = blockIdx.x * blockDim.x + threadIdx.x;
    if (idx >= N_CHUNKS * 2 * 8 * 32) return;
    int lane = idx & 31;
    int q = (idx >> 5) & 7;
    int s = (idx >> 8) & 1;
    int chunk = idx >> 9;
    int t4 = lane & 3, g = lane >> 2;

    const float* Wsrc;
    int kbase;
    if (chunk < 12) {
        Wsrc = W0;
        kbase = chunk * 32;
    } else {
        int c2 = chunk - 12;
        Wsrc = W + (size_t)(c2 >> 2) * 128 * 128;
        kbase = (c2 & 3) * 32;
    }
    int k0 = kbase + s * 16 + 2 * t4;
    int n0 = (2 * q) * 8 + g;
    int n1 = n0 + 8;

    uint4 o;
    o.x = pack_h2(__ldg(&Wsrc[(size_t)k0 * 128 + n0]),       __ldg(&Wsrc[(size_t)(k0 + 1) * 128 + n0]));
    o.y = pack_h2(__ldg(&Wsrc[(size_t)(k0 + 8) * 128 + n0]), __ldg(&Wsrc[(size_t)(k0 + 9) * 128 + n0]));
    o.z = pack_h2(__ldg(&Wsrc[(size_t)k0 * 128 + n1]),       __ldg(&Wsrc[(size_t)(k0 + 1) * 128 + n1]));
    o.w = pack_h2(__ldg(&Wsrc[(size_t)(k0 + 8) * 128 + n1]), __ldg(&Wsrc[(size_t)(k0 + 9) * 128 + n1]));
    WF[idx] = o;
}

// ---------------------------------------------------------------------------
// Histogram (8 edges/thread)
// ---------------------------------------------------------------------------
__global__ void hist_kernel(const int* __restrict__ ei, int* __restrict__ cnt) {
    int i = blockIdx.x * blockDim.x + threadIdx.x;
    if (i >= NE / 8) return;
    int4 s0 = __ldg((const int4*)ei + 2 * i);
    int4 s1 = __ldg((const int4*)ei + 2 * i + 1);
    int4 t0 = __ldg((const int4*)(ei + NE) + 2 * i);
    int4 t1 = __ldg((const int4*)(ei + NE) + 2 * i + 1);
    atomicAdd(&cnt[t0.x], 1); atomicAdd(&cnt[t0.y], 1);
    atomicAdd(&cnt[t0.z], 1); atomicAdd(&cnt[t0.w], 1);
    atomicAdd(&cnt[t1.x], 1); atomicAdd(&cnt[t1.y], 1);
    atomicAdd(&cnt[t1.z], 1); atomicAdd(&cnt[t1.w], 1);
    atomicAdd(&cnt[NN + s0.x], 1); atomicAdd(&cnt[NN + s0.y], 1);
    atomicAdd(&cnt[NN + s0.z], 1); atomicAdd(&cnt[NN + s0.w], 1);
    atomicAdd(&cnt[NN + s1.x], 1); atomicAdd(&cnt[NN + s1.y], 1);
    atomicAdd(&cnt[NN + s1.z], 1); atomicAdd(&cnt[NN + s1.w], 1);
}

// ---------------------------------------------------------------------------
// Parallel segment allocation (offsets unordered)
// ---------------------------------------------------------------------------
__global__ void alloc_kernel(const int* __restrict__ cnt,
                             int* __restrict__ offin, int* __restrict__ curin,
                             int* __restrict__ offout, int* __restrict__ curout,
                             int* __restrict__ cursors) {
    int i = blockIdx.x * blockDim.x + threadIdx.x;
    if (i >= 2 * NN) return;
    int lane = threadIdx.x & 31;
    int c = cnt[i];
    int inc = c;
#pragma unroll
    for (int o = 1; o < 32; o <<= 1) {
        int v = __shfl_up_sync(0xFFFFFFFFu, inc, o);
        if (lane >= o) inc += v;
    }
    int tot = __shfl_sync(0xFFFFFFFFu, inc, 31);
    int ex = inc - c;
    int half = (i < NN) ? 0 : 1;
    int base = 0;
    if (lane == 0) base = atomicAdd(&cursors[half], tot);
    base = __shfl_sync(0xFFFFFFFFu, base, 0);
    int off = base + ex;
    if (half == 0) { offin[i] = off; curin[i] = off; }
    else           { offout[i - NN] = off; curout[i - NN] = off; }
}

// ---------------------------------------------------------------------------
// Fill CSR lists (8 edges/thread, atomics batched before stores)
// ---------------------------------------------------------------------------
__global__ void fill_kernel(const int* __restrict__ ei, const float* __restrict__ e,
                            int* __restrict__ curin, int* __restrict__ curout,
                            int2* __restrict__ lin, int2* __restrict__ lout) {
    int i = blockIdx.x * blockDim.x + threadIdx.x;
    if (i >= NE / 8) return;
    int4 s0 = __ldg((const int4*)ei + 2 * i);
    int4 s1 = __ldg((const int4*)ei + 2 * i + 1);
    int4 t0 = __ldg((const int4*)(ei + NE) + 2 * i);
    int4 t1 = __ldg((const int4*)(ei + NE) + 2 * i + 1);
    float4 w0 = __ldg((const float4*)e + 2 * i);
    float4 w1 = __ldg((const float4*)e + 2 * i + 1);
    int ss[8] = {s0.x, s0.y, s0.z, s0.w, s1.x, s1.y, s1.z, s1.w};
    int tt[8] = {t0.x, t0.y, t0.z, t0.w, t1.x, t1.y, t1.z, t1.w};
    float ww[8] = {w0.x, w0.y, w0.z, w0.w, w1.x, w1.y, w1.z, w1.w};

    int pin[8], pout[8];
#pragma unroll
    for (int u = 0; u < 8; u++) pin[u] = atomicAdd(&curin[tt[u]], 1);
#pragma unroll
    for (int u = 0; u < 8; u++) pout[u] = atomicAdd(&curout[ss[u]], 1);
#pragma unroll
    for (int u = 0; u < 8; u++) lin[pin[u]] = make_int2(ss[u], __float_as_int(ww[u]));
#pragma unroll
    for (int u = 0; u < 8; u++) lout[pout[u]] = make_int2(tt[u], __float_as_int(ww[u]));
}

// ---------------------------------------------------------------------------
// Gather (fp16): one warp per (node, dir). Permutation-transparent.
// ---------------------------------------------------------------------------
__global__ __launch_bounds__(256) void gather_kernel(
    const uint32_t* __restrict__ xh, const int* __restrict__ cnt,
    const int* __restrict__ offin, const int2* __restrict__ lin,
    const int* __restrict__ offout, const int2* __restrict__ lout,
    uint32_t* __restrict__ mih, uint32_t* __restrict__ moh) {
    int wg = (blockIdx.x * blockDim.x + threadIdx.x) >> 5;
    int lane = threadIdx.x & 31;
    if (wg >= 2 * NN) return;

    const int* off;
    const int2* lst;
    uint32_t* dst;
    int node, cofs;
    if (wg < NN) { node = wg; off = offin; lst = lin; dst = mih; cofs = 0; }
    else         { node = wg - NN; off = offout; lst = lout; dst = moh; cofs = NN; }

    int beg = off[node];
    int end = beg + cnt[cofs + node];

    float2 acc0 = make_float2(0.f, 0.f);
    float2 acc1 = make_float2(0.f, 0.f);

    int j = beg;
    for (; j + 8 <= end; j += 8) {
        int2 p[8];
#pragma unroll
        for (int u = 0; u < 8; u++) p[u] = __ldg(&lst[j + u]);
        uint2 v[8];
#pragma unroll
        for (int u = 0; u < 8; u++)
            v[u] = __ldg((const uint2*)(xh + (size_t)p[u].x * 64) + lane);
#pragma unroll
        for (int u = 0; u < 8; u++) {
            float w = __int_as_float(p[u].y);
            float2 f0 = __half22float2(*(__half2*)&v[u].x);
            float2 f1 = __half22float2(*(__half2*)&v[u].y);
            acc0.x = fmaf(w, f0.x, acc0.x); acc0.y = fmaf(w, f0.y, acc0.y);
            acc1.x = fmaf(w, f1.x, acc1.x); acc1.y = fmaf(w, f1.y, acc1.y);
        }
    }
    for (; j < end; j++) {
        int2 p0 = __ldg(&lst[j]);
        uint2 v0 = __ldg((const uint2*)(xh + (size_t)p0.x * 64) + lane);
        float w = __int_as_float(p0.y);
        float2 f0 = __half22float2(*(__half2*)&v0.x);
        float2 f1 = __half22float2(*(__half2*)&v0.y);
        acc0.x = fmaf(w, f0.x, acc0.x); acc0.y = fmaf(w, f0.y, acc0.y);
        acc1.x = fmaf(w, f1.x, acc1.x); acc1.y = fmaf(w, f1.y, acc1.y);
    }

    uint2 o;
    o.x = pack_h2(acc0.x, acc0.y);
    o.y = pack_h2(acc1.x, acc1.y);
    ((uint2*)(dst + (size_t)node * 64))[lane] = o;
}

// ---------------------------------------------------------------------------
// Fused 4-layer MLP, fp16 m16n8k16. A-fragment pairs are single 8B loads
// (permuted layout). 2 blocks/SM — 3 caused register spills (round 9).
// ---------------------------------------------------------------------------
#define MMA16(cj, A0r, A1r, A2r, A3r, B0r, B1r)                                  \
    asm volatile(                                                                \
        "mma.sync.aligned.m16n8k16.row.col.f32.f16.f16.f32 "                     \
        "{%0,%1,%2,%3}, {%4,%5,%6,%7}, {%8,%9}, {%0,%1,%2,%3};"                  \
        : "+f"(cj[0]), "+f"(cj[1]), "+f"(cj[2]), "+f"(cj[3])                     \
        : "r"(A0r), "r"(A1r), "r"(A2r), "r"(A3r), "r"(B0r), "r"(B1r))

__global__ __launch_bounds__(MLP_THREADS, 2) void mlp_fused(
    const uint32_t* __restrict__ A0h, const uint32_t* __restrict__ A1h,
    const uint32_t* __restrict__ A2h,
    const uint4* __restrict__ WF,
    const float* __restrict__ b0v, const float* __restrict__ g0v,
    const float* __restrict__ be0v,
    const float* __restrict__ bv, const float* __restrict__ gv,
    const float* __restrict__ bev,
    float* __restrict__ out)
{
    extern __shared__ uint32_t smem[];
    const int tid = threadIdx.x;
    const int lane = tid & 31;
    const int wid = tid >> 5;
    const int g = lane >> 2;
    const int t4 = lane & 3;
    const int row0 = blockIdx.x * ROWS_PER_BLOCK + wid * 32;

    uint32_t* Hw = smem + wid * 32 * HS16;   // per-warp slab [32][HS16] half2

    float c[2][16][4];
#pragma unroll
    for (int t = 0; t < 2; t++)
#pragma unroll
        for (int j = 0; j < 16; j++)
#pragma unroll
            for (int q = 0; q < 4; q++) c[t][j][q] = 0.f;

    int r00 = row0 + g;
    int r10 = row0 + 16 + g;
    size_t cr00 = (size_t)(r00 < NN ? r00 : 0) * 64;
    size_t cr01 = (size_t)((r00 + 8) < NN ? (r00 + 8) : 0) * 64;
    size_t cr10 = (size_t)(r10 < NN ? r10 : 0) * 64;
    size_t cr11 = (size_t)((r10 + 8) < NN ? (r10 + 8) : 0) * 64;

    // ---------------- Layer 0: K = 384 over {mih, moh, xh} ----------------
    const uint32_t* Ap[3] = {A0h, A1h, A2h};
#pragma unroll 1
    for (int m = 0; m < 3; m++) {
        const uint32_t* A = Ap[m];
#pragma unroll
        for (int kc = 0; kc < 4; kc++) {
            int chunk = m * 4 + kc;
#pragma unroll
            for (int s = 0; s < 2; s++) {
                int group8 = (kc * 2 + s) * 8;
                uint32_t a0[4], a1[4];
                uint2 v;
                v = __ldg((const uint2*)(A + cr00 + group8) + t4); a0[0] = v.x; a0[2] = v.y;
                v = __ldg((const uint2*)(A + cr01 + group8) + t4); a0[1] = v.x; a0[3] = v.y;
                v = __ldg((const uint2*)(A + cr10 + group8) + t4); a1[0] = v.x; a1[2] = v.y;
                v = __ldg((const uint2*)(A + cr11 + group8) + t4); a1[1] = v.x; a1[3] = v.y;
                const uint4* wfk = WF + ((size_t)(chunk * 2 + s) << 8);
#pragma unroll
                for (int q = 0; q < 8; q++) {
                    uint4 bb = __ldg(&wfk[(q << 5) + lane]);
                    MMA16(c[0][2 * q],     a0[0], a0[1], a0[2], a0[3], bb.x, bb.y);
                    MMA16(c[0][2 * q + 1], a0[0], a0[1], a0[2], a0[3], bb.z, bb.w);
                    MMA16(c[1][2 * q],     a1[0], a1[1], a1[2], a1[3], bb.x, bb.y);
                    MMA16(c[1][2 * q + 1], a1[0], a1[1], a1[2], a1[3], bb.z, bb.w);
                }
            }
        }
    }

    // ---------------- 4 epilogues + 3 inner layers ----------------
#pragma unroll 1
    for (int l = 0; l < 4; l++) {
        const float* bias  = (l == 0) ? b0v  : bv  + (l - 1) * 128;
        const float* gamma = (l == 0) ? g0v  : gv  + (l - 1) * 128;
        const float* beta  = (l == 0) ? be0v : bev + (l - 1) * 128;

        float s[2][2], qq[2][2];
#pragma unroll
        for (int t = 0; t < 2; t++) { s[t][0]=s[t][1]=qq[t][0]=qq[t][1]=0.f; }

#pragma unroll
        for (int j = 0; j < 16; j++) {
            int col = j * 8 + 2 * t4;
            float2 bb = __ldg((const float2*)(bias + col));
#pragma unroll
            for (int t = 0; t < 2; t++) {
                c[t][j][0] += bb.x; c[t][j][1] += bb.y;
                c[t][j][2] += bb.x; c[t][j][3] += bb.y;
                s[t][0]  += c[t][j][0] + c[t][j][1];
                qq[t][0] += c[t][j][0] * c[t][j][0] + c[t][j][1] * c[t][j][1];
                s[t][1]  += c[t][j][2] + c[t][j][3];
                qq[t][1] += c[t][j][2] * c[t][j][2] + c[t][j][3] * c[t][j][3];
            }
        }
#pragma unroll
        for (int o = 1; o <= 2; o <<= 1) {
#pragma unroll
            for (int t = 0; t < 2; t++) {
                s[t][0]  += __shfl_xor_sync(0xFFFFFFFFu, s[t][0], o);
                qq[t][0] += __shfl_xor_sync(0xFFFFFFFFu, qq[t][0], o);
                s[t][1]  += __shfl_xor_sync(0xFFFFFFFFu, s[t][1], o);
                qq[t][1] += __shfl_xor_sync(0xFFFFFFFFu, qq[t][1], o);
            }
        }
        float mean[2][2], rstd[2][2];
#pragma unroll
        for (int t = 0; t < 2; t++)
#pragma unroll
            for (int h = 0; h < 2; h++) {
                mean[t][h] = s[t][h] * (1.f / 128.f);
                rstd[t][h] = rsqrtf(qq[t][h] * (1.f / 128.f) - mean[t][h] * mean[t][h] + 1e-5f);
            }

        if (l == 3) {
#pragma unroll
            for (int j = 0; j < 16; j++) {
                int col = j * 8 + 2 * t4;
                float2 gg = __ldg((const float2*)(gamma + col));
                float2 ee = __ldg((const float2*)(beta + col));
#pragma unroll
                for (int t = 0; t < 2; t++) {
                    int ra = row0 + t * 16 + g;
                    int rb = ra + 8;
                    if (ra < NN) {
                        float2 o1;
                        o1.x = fast_tanh((c[t][j][0] - mean[t][0]) * rstd[t][0] * gg.x + ee.x);
                        o1.y = fast_tanh((c[t][j][1] - mean[t][0]) * rstd[t][0] * gg.y + ee.y);
                        *(float2*)(out + (size_t)ra * DD + col) = o1;
                    }
                    if (rb < NN) {
                        float2 o2;
                        o2.x = fast_tanh((c[t][j][2] - mean[t][1]) * rstd[t][1] * gg.x + ee.x);
                        o2.y = fast_tanh((c[t][j][3] - mean[t][1]) * rstd[t][1] * gg.y + ee.y);
                        *(float2*)(out + (size_t)rb * DD + col) = o2;
                    }
                }
            }
            break;
        }

        // Write h (half2) into per-warp smem slab in PERMUTED layout:
        // logical word (j*4 + t4) -> stored index (j>>1)*8 + 2*t4 + (j&1).
        __syncwarp();
#pragma unroll
        for (int j = 0; j < 16; j++) {
            int col = j * 8 + 2 * t4;
            float2 gg = __ldg((const float2*)(gamma + col));
            float2 ee = __ldg((const float2*)(beta + col));
            int ci = (j >> 1) * 8 + 2 * t4 + (j & 1);
#pragma unroll
            for (int t = 0; t < 2; t++) {
                float h00 = fast_tanh((c[t][j][0] - mean[t][0]) * rstd[t][0] * gg.x + ee.x);
                float h01 = fast_tanh((c[t][j][1] - mean[t][0]) * rstd[t][0] * gg.y + ee.y);
                float h10 = fast_tanh((c[t][j][2] - mean[t][1]) * rstd[t][1] * gg.x + ee.x);
                float h11 = fast_tanh((c[t][j][3] - mean[t][1]) * rstd[t][1] * gg.y + ee.y);
                Hw[(t * 16 + g) * HS16 + ci]     = pack_h2(h00, h01);
                Hw[(t * 16 + g + 8) * HS16 + ci] = pack_h2(h10, h11);
                c[t][j][0] = 0.f; c[t][j][1] = 0.f;
                c[t][j][2] = 0.f; c[t][j][3] = 0.f;
            }
        }
        __syncwarp();

        // Next layer GEMM: h (in Hw, permuted) @ W[l], K = 128
#pragma unroll
        for (int kc = 0; kc < 4; kc++) {
            int chunk = 12 + l * 4 + kc;
#pragma unroll
            for (int s = 0; s < 2; s++) {
                int group8 = (kc * 2 + s) * 8;
                uint32_t a0[4], a1[4];
                uint2 v;
                v = *(const uint2*)(Hw + (g) * HS16 + group8 + 2 * t4);      a0[0] = v.x; a0[2] = v.y;
                v = *(const uint2*)(Hw + (g + 8) * HS16 + group8 + 2 * t4);  a0[1] = v.x; a0[3] = v.y;
                v = *(const uint2*)(Hw + (16 + g) * HS16 + group8 + 2 * t4); a1[0] = v.x; a1[2] = v.y;
                v = *(const uint2*)(Hw + (24 + g) * HS16 + group8 + 2 * t4); a1[1] = v.x; a1[3] = v.y;
                const uint4* wfk = WF + ((size_t)(chunk * 2 + s) << 8);
#pragma unroll
                for (int q = 0; q < 8; q++) {
                    uint4 bb = __ldg(&wfk[(q << 5) + lane]);
                    MMA16(c[0][2 * q],     a0[0], a0[1], a0[2], a0[3], bb.x, bb.y);
                    MMA16(c[0][2 * q + 1], a0[0], a0[1], a0[2], a0[3], bb.z, bb.w);
                    MMA16(c[1][2 * q],     a1[0], a1[1], a1[2], a1[3], bb.x, bb.y);
                    MMA16(c[1][2 * q + 1], a1[0], a1[1], a1[2], a1[3], bb.z, bb.w);
                }
            }
        }
    }
}

// ---------------------------------------------------------------------------
extern "C" void kernel_launch(void* const* d_in, const int* in_sizes, int n_in,
                              void* d_out, int out_size) {
    const float* x   = (const float*)d_in[0];
    const float* e   = (const float*)d_in[1];
    const int*   ei  = (const int*)d_in[2];
    const float* W0  = (const float*)d_in[3];
    const float* b0  = (const float*)d_in[4];
    const float* g0  = (const float*)d_in[5];
    const float* be0 = (const float*)d_in[6];
    const float* W   = (const float*)d_in[7];
    const float* b   = (const float*)d_in[8];
    const float* g   = (const float*)d_in[9];
    const float* be  = (const float*)d_in[10];
    float* out = (float*)d_out;

    uint32_t *xh, *mih, *moh;
    int *cnt, *offin, *offout, *curin, *curout;
    int2 *lin, *lout;
    uint4* wf;
    cudaGetSymbolAddress((void**)&xh, g_xh);
    cudaGetSymbolAddress((void**)&mih, g_mih);
    cudaGetSymbolAddress((void**)&moh, g_moh);
    cudaGetSymbolAddress((void**)&cnt, g_cnt);
    cudaGetSymbolAddress((void**)&offin, g_off_in);
    cudaGetSymbolAddress((void**)&offout, g_off_out);
    cudaGetSymbolAddress((void**)&curin, g_cur_in);
    cudaGetSymbolAddress((void**)&curout, g_cur_out);
    cudaGetSymbolAddress((void**)&lin, g_lst_in);
    cudaGetSymbolAddress((void**)&lout, g_lst_out);
    cudaGetSymbolAddress((void**)&wf, g_wfrag);
    int* cursors = cnt + 2 * NN;

    const int smem_bytes = 4 * 32 * HS16 * 4;   // 4 warps x 32 rows x 68 words
    cudaFuncSetAttribute(mlp_fused,
                         cudaFuncAttributeMaxDynamicSharedMemorySize,
                         smem_bytes);

    cudaMemsetAsync(cnt, 0, (2 * NN + 2) * sizeof(int));

    xconv_kernel<<<(NN * 8 + 255) / 256, 256>>>(x, xh);
    wfrag_kernel<<<(N_CHUNKS * 512 + 255) / 256, 256>>>(W0, W, wf);
    hist_kernel<<<(NE / 8 + 255) / 256, 256>>>(ei, cnt);
    alloc_kernel<<<(2 * NN + 255) / 256, 256>>>(cnt, offin, curin, offout, curout, cursors);
    fill_kernel<<<(NE / 8 + 255) / 256, 256>>>(ei, e, curin, curout, lin, lout);

    {
        long long warps = 2LL * NN;
        int blocks = (int)((warps * 32 + 255) / 256);
        gather_kernel<<<blocks, 256>>>(xh, cnt, offin, lin, offout, lout, mih, moh);
    }

    const int gblocks = (NN + ROWS_PER_BLOCK - 1) / ROWS_PER_BLOCK;  // 782
    mlp_fused<<<gblocks, MLP_THREADS, smem_bytes>>>(
        mih, moh, xh, wf, b0, g0, be0, b, g, be, out);
}

// round 13
// speedup vs baseline: 1.1180x; 1.0649x over previous
#include <cuda_runtime.h>
#include <cuda_fp16.h>
#include <math.h>
#include <stdint.h>

#define NN 100000
#define DD 128
#define NE 1600000

#define MLP_THREADS 128          // 4 warps; each warp owns 32 rows
#define ROWS_PER_BLOCK 128
#define N_CHUNKS 24              // 12 layer-0 (384 k) + 12 inner (3 x 128 k)
#define HS16 68                  // H slab row stride in uint32 (half2) units

// prep_kernel block ranges
#define PREP_XCONV_BLOCKS 12500  // NN*128/4 float4s / 256 threads
#define PREP_WFRAG_BLOCKS 48     // N_CHUNKS*512/256
#define PREP_HIST_BLOCKS  782    // ceil(NE/8/256)
#define PREP_BLOCKS (PREP_XCONV_BLOCKS + PREP_WFRAG_BLOCKS + PREP_HIST_BLOCKS)

// Scratch (allocation-free rule: __device__ globals)
__device__ uint32_t g_xh[(size_t)NN * 64];    // x as half2 pairs (plain layout)
__device__ uint32_t g_mih[(size_t)NN * 64];
__device__ uint32_t g_moh[(size_t)NN * 64];

__device__ int   g_cnt[2 * NN + 2];   // [2NN..2NN+2): global cursors
__device__ int   g_off_in[NN];
__device__ int   g_off_out[NN];
__device__ int   g_cur_in[NN];
__device__ int   g_cur_out[NN];
__device__ int2  g_lst_in[NE];
__device__ int2  g_lst_out[NE];
__device__ uint4 g_wfrag[N_CHUNKS * 2 * 8 * 32];   // fp16 frag-major weights

// ---------------------------------------------------------------------------
__device__ __forceinline__ float fast_tanh(float x) {
    float ax = fabsf(x);
    float t = __expf(-2.f * ax);
    float r = (1.f - t) * __frcp_rn(1.f + t);
    return copysignf(r, x);
}

__device__ __forceinline__ uint32_t pack_h2(float a, float b) {
    __half2 h = __floats2half2_rn(a, b);
    return *(uint32_t*)&h;
}

// ---------------------------------------------------------------------------
// Fused prep: xconv (blocks [0,12500)), wfrag (next 48), hist (last 782).
// ---------------------------------------------------------------------------
__global__ void prep_kernel(const float* __restrict__ x, uint32_t* __restrict__ xh,
                            const float* __restrict__ W0, const float* __restrict__ W,
                            uint4* __restrict__ WF,
                            const int* __restrict__ ei, int* __restrict__ cnt) {
    int b = blockIdx.x;
    if (b < PREP_XCONV_BLOCKS) {
        // x fp32 -> plain fp16x2 (one float4 per thread)
        int i = b * 256 + threadIdx.x;   // i < NN*32 always (12500*256 == NN*32)
        float4 v = __ldg((const float4*)x + i);
        uint2 o;
        o.x = pack_h2(v.x, v.y);
        o.y = pack_h2(v.z, v.w);
        ((uint2*)xh)[i] = o;
        return;
    }
    b -= PREP_XCONV_BLOCKS;
    if (b < PREP_WFRAG_BLOCKS) {
        // W0 [384,128] + W [3,128,128] -> fp16 fragment-major for m16n8k16
        int idx = b * 256 + threadIdx.x;   // idx < N_CHUNKS*512 always
        int lane = idx & 31;
        int q = (idx >> 5) & 7;
        int s = (idx >> 8) & 1;
        int chunk = idx >> 9;
        int t4 = lane & 3, g = lane >> 2;

        const float* Wsrc;
        int kbase;
        if (chunk < 12) {
            Wsrc = W0;
            kbase = chunk * 32;
        } else {
            int c2 = chunk - 12;
            Wsrc = W + (size_t)(c2 >> 2) * 128 * 128;
            kbase = (c2 & 3) * 32;
        }
        int k0 = kbase + s * 16 + 2 * t4;
        int n0 = (2 * q) * 8 + g;
        int n1 = n0 + 8;

        uint4 o;
        o.x = pack_h2(__ldg(&Wsrc[(size_t)k0 * 128 + n0]),       __ldg(&Wsrc[(size_t)(k0 + 1) * 128 + n0]));
        o.y = pack_h2(__ldg(&Wsrc[(size_t)(k0 + 8) * 128 + n0]), __ldg(&Wsrc[(size_t)(k0 + 9) * 128 + n0]));
        o.z = pack_h2(__ldg(&Wsrc[(size_t)k0 * 128 + n1]),       __ldg(&Wsrc[(size_t)(k0 + 1) * 128 + n1]));
        o.w = pack_h2(__ldg(&Wsrc[(size_t)(k0 + 8) * 128 + n1]), __ldg(&Wsrc[(size_t)(k0 + 9) * 128 + n1]));
        WF[idx] = o;
        return;
    }
    b -= PREP_WFRAG_BLOCKS;
    {
        // Histogram (8 edges/thread)
        int i = b * 256 + threadIdx.x;
        if (i >= NE / 8) return;
        int4 s0 = __ldg((const int4*)ei + 2 * i);
        int4 s1 = __ldg((const int4*)ei + 2 * i + 1);
        int4 t0 = __ldg((const int4*)(ei + NE) + 2 * i);
        int4 t1 = __ldg((const int4*)(ei + NE) + 2 * i + 1);
        atomicAdd(&cnt[t0.x], 1); atomicAdd(&cnt[t0.y], 1);
        atomicAdd(&cnt[t0.z], 1); atomicAdd(&cnt[t0.w], 1);
        atomicAdd(&cnt[t1.x], 1); atomicAdd(&cnt[t1.y], 1);
        atomicAdd(&cnt[t1.z], 1); atomicAdd(&cnt[t1.w], 1);
        atomicAdd(&cnt[NN + s0.x], 1); atomicAdd(&cnt[NN + s0.y], 1);
        atomicAdd(&cnt[NN + s0.z], 1); atomicAdd(&cnt[NN + s0.w], 1);
        atomicAdd(&cnt[NN + s1.x], 1); atomicAdd(&cnt[NN + s1.y], 1);
        atomicAdd(&cnt[NN + s1.z], 1); atomicAdd(&cnt[NN + s1.w], 1);
    }
}

// ---------------------------------------------------------------------------
// Parallel segment allocation (offsets unordered)
// ---------------------------------------------------------------------------
__global__ void alloc_kernel(const int* __restrict__ cnt,
                             int* __restrict__ offin, int* __restrict__ curin,
                             int* __restrict__ offout, int* __restrict__ curout,
                             int* __restrict__ cursors) {
    int i = blockIdx.x * blockDim.x + threadIdx.x;
    if (i >= 2 * NN) return;
    int lane = threadIdx.x & 31;
    int c = cnt[i];
    int inc = c;
#pragma unroll
    for (int o = 1; o < 32; o <<= 1) {
        int v = __shfl_up_sync(0xFFFFFFFFu, inc, o);
        if (lane >= o) inc += v;
    }
    int tot = __shfl_sync(0xFFFFFFFFu, inc, 31);
    int ex = inc - c;
    int half = (i < NN) ? 0 : 1;
    int base = 0;
    if (lane == 0) base = atomicAdd(&cursors[half], tot);
    base = __shfl_sync(0xFFFFFFFFu, base, 0);
    int off = base + ex;
    if (half == 0) { offin[i] = off; curin[i] = off; }
    else           { offout[i - NN] = off; curout[i - NN] = off; }
}

// ---------------------------------------------------------------------------
// Fill CSR lists: 16 edges/thread, all atomics issued before stores (MLP)
// ---------------------------------------------------------------------------
__global__ void fill_kernel(const int* __restrict__ ei, const float* __restrict__ e,
                            int* __restrict__ curin, int* __restrict__ curout,
                            int2* __restrict__ lin, int2* __restrict__ lout) {
    int i = blockIdx.x * blockDim.x + threadIdx.x;
    if (i >= NE / 16) return;
    int ss[16], tt[16];
    float ww[16];
#pragma unroll
    for (int v4 = 0; v4 < 4; v4++) {
        int4 s = __ldg((const int4*)ei + 4 * i + v4);
        int4 t = __ldg((const int4*)(ei + NE) + 4 * i + v4);
        float4 w = __ldg((const float4*)e + 4 * i + v4);
        ss[4 * v4 + 0] = s.x; ss[4 * v4 + 1] = s.y; ss[4 * v4 + 2] = s.z; ss[4 * v4 + 3] = s.w;
        tt[4 * v4 + 0] = t.x; tt[4 * v4 + 1] = t.y; tt[4 * v4 + 2] = t.z; tt[4 * v4 + 3] = t.w;
        ww[4 * v4 + 0] = w.x; ww[4 * v4 + 1] = w.y; ww[4 * v4 + 2] = w.z; ww[4 * v4 + 3] = w.w;
    }
    int pin[16], pout[16];
#pragma unroll
    for (int u = 0; u < 16; u++) pin[u] = atomicAdd(&curin[tt[u]], 1);
#pragma unroll
    for (int u = 0; u < 16; u++) pout[u] = atomicAdd(&curout[ss[u]], 1);
#pragma unroll
    for (int u = 0; u < 16; u++) lin[pin[u]] = make_int2(ss[u], __float_as_int(ww[u]));
#pragma unroll
    for (int u = 0; u < 16; u++) lout[pout[u]] = make_int2(tt[u], __float_as_int(ww[u]));
}

// ---------------------------------------------------------------------------
// Gather (fp16): one warp per (node, dir). Round-8 champion version.
// ---------------------------------------------------------------------------
__global__ __launch_bounds__(256) void gather_kernel(
    const uint32_t* __restrict__ xh, const int* __restrict__ cnt,
    const int* __restrict__ offin, const int2* __restrict__ lin,
    const int* __restrict__ offout, const int2* __restrict__ lout,
    uint32_t* __restrict__ mih, uint32_t* __restrict__ moh) {
    int wg = (blockIdx.x * blockDim.x + threadIdx.x) >> 5;
    int lane = threadIdx.x & 31;
    if (wg >= 2 * NN) return;

    const int* off;
    const int2* lst;
    uint32_t* dst;
    int node, cofs;
    if (wg < NN) { node = wg; off = offin; lst = lin; dst = mih; cofs = 0; }
    else         { node = wg - NN; off = offout; lst = lout; dst = moh; cofs = NN; }

    int beg = off[node];
    int end = beg + cnt[cofs + node];

    float2 acc0 = make_float2(0.f, 0.f);
    float2 acc1 = make_float2(0.f, 0.f);

    int j = beg;
    for (; j + 8 <= end; j += 8) {
        int2 p[8];
#pragma unroll
        for (int u = 0; u < 8; u++) p[u] = __ldg(&lst[j + u]);
        uint2 v[8];
#pragma unroll
        for (int u = 0; u < 8; u++)
            v[u] = __ldg((const uint2*)(xh + (size_t)p[u].x * 64) + lane);
#pragma unroll
        for (int u = 0; u < 8; u++) {
            float w = __int_as_float(p[u].y);
            float2 f0 = __half22float2(*(__half2*)&v[u].x);
            float2 f1 = __half22float2(*(__half2*)&v[u].y);
            acc0.x = fmaf(w, f0.x, acc0.x); acc0.y = fmaf(w, f0.y, acc0.y);
            acc1.x = fmaf(w, f1.x, acc1.x); acc1.y = fmaf(w, f1.y, acc1.y);
        }
    }
    for (; j < end; j++) {
        int2 p0 = __ldg(&lst[j]);
        uint2 v0 = __ldg((const uint2*)(xh + (size_t)p0.x * 64) + lane);
        float w = __int_as_float(p0.y);
        float2 f0 = __half22float2(*(__half2*)&v0.x);
        float2 f1 = __half22float2(*(__half2*)&v0.y);
        acc0.x = fmaf(w, f0.x, acc0.x); acc0.y = fmaf(w, f0.y, acc0.y);
        acc1.x = fmaf(w, f1.x, acc1.x); acc1.y = fmaf(w, f1.y, acc1.y);
    }

    uint2 o;
    o.x = pack_h2(acc0.x, acc0.y);
    o.y = pack_h2(acc1.x, acc1.y);
    ((uint2*)(dst + (size_t)node * 64))[lane] = o;
}

// ---------------------------------------------------------------------------
// Fused 4-layer MLP, fp16 m16n8k16 — round-8 champion version, unchanged.
// ---------------------------------------------------------------------------
#define MMA16(cj, A0r, A1r, A2r, A3r, B0r, B1r)                                  \
    asm volatile(                                                                \
        "mma.sync.aligned.m16n8k16.row.col.f32.f16.f16.f32 "                     \
        "{%0,%1,%2,%3}, {%4,%5,%6,%7}, {%8,%9}, {%0,%1,%2,%3};"                  \
        : "+f"(cj[0]), "+f"(cj[1]), "+f"(cj[2]), "+f"(cj[3])                     \
        : "r"(A0r), "r"(A1r), "r"(A2r), "r"(A3r), "r"(B0r), "r"(B1r))

__global__ __launch_bounds__(MLP_THREADS, 2) void mlp_fused(
    const uint32_t* __restrict__ A0h, const uint32_t* __restrict__ A1h,
    const uint32_t* __restrict__ A2h,
    const uint4* __restrict__ WF,
    const float* __restrict__ b0v, const float* __restrict__ g0v,
    const float* __restrict__ be0v,
    const float* __restrict__ bv, const float* __restrict__ gv,
    const float* __restrict__ bev,
    float* __restrict__ out)
{
    extern __shared__ uint32_t smem[];
    const int tid = threadIdx.x;
    const int lane = tid & 31;
    const int wid = tid >> 5;
    const int g = lane >> 2;
    const int t4 = lane & 3;
    const int row0 = blockIdx.x * ROWS_PER_BLOCK + wid * 32;

    uint32_t* Hw = smem + wid * 32 * HS16;   // per-warp slab [32][HS16] half2

    float c[2][16][4];
#pragma unroll
    for (int t = 0; t < 2; t++)
#pragma unroll
        for (int j = 0; j < 16; j++)
#pragma unroll
            for (int q = 0; q < 4; q++) c[t][j][q] = 0.f;

    int r00 = row0 + g;
    int r10 = row0 + 16 + g;
    size_t cr00 = (size_t)(r00 < NN ? r00 : 0) * 64;
    size_t cr01 = (size_t)((r00 + 8) < NN ? (r00 + 8) : 0) * 64;
    size_t cr10 = (size_t)(r10 < NN ? r10 : 0) * 64;
    size_t cr11 = (size_t)((r10 + 8) < NN ? (r10 + 8) : 0) * 64;

    // ---------------- Layer 0: K = 384 over {mih, moh, xh} ----------------
    const uint32_t* Ap[3] = {A0h, A1h, A2h};
#pragma unroll 1
    for (int m = 0; m < 3; m++) {
        const uint32_t* A = Ap[m];
#pragma unroll
        for (int kc = 0; kc < 4; kc++) {
            int chunk = m * 4 + kc;
#pragma unroll
            for (int s = 0; s < 2; s++) {
                int kidx = kc * 16 + s * 8 + t4;       // uint32 (half2) index
                uint32_t a0[4], a1[4];
                a0[0] = __ldg(A + cr00 + kidx);
                a0[1] = __ldg(A + cr01 + kidx);
                a0[2] = __ldg(A + cr00 + kidx + 4);
                a0[3] = __ldg(A + cr01 + kidx + 4);
                a1[0] = __ldg(A + cr10 + kidx);
                a1[1] = __ldg(A + cr11 + kidx);
                a1[2] = __ldg(A + cr10 + kidx + 4);
                a1[3] = __ldg(A + cr11 + kidx + 4);
                const uint4* wfk = WF + ((size_t)(chunk * 2 + s) << 8);
#pragma unroll
                for (int q = 0; q < 8; q++) {
                    uint4 bb = __ldg(&wfk[(q << 5) + lane]);
                    MMA16(c[0][2 * q],     a0[0], a0[1], a0[2], a0[3], bb.x, bb.y);
                    MMA16(c[0][2 * q + 1], a0[0], a0[1], a0[2], a0[3], bb.z, bb.w);
                    MMA16(c[1][2 * q],     a1[0], a1[1], a1[2], a1[3], bb.x, bb.y);
                    MMA16(c[1][2 * q + 1], a1[0], a1[1], a1[2], a1[3], bb.z, bb.w);
                }
            }
        }
    }

    // ---------------- 4 epilogues + 3 inner layers ----------------
#pragma unroll 1
    for (int l = 0; l < 4; l++) {
        const float* bias  = (l == 0) ? b0v  : bv  + (l - 1) * 128;
        const float* gamma = (l == 0) ? g0v  : gv  + (l - 1) * 128;
        const float* beta  = (l == 0) ? be0v : bev + (l - 1) * 128;

        float s[2][2], qq[2][2];
#pragma unroll
        for (int t = 0; t < 2; t++) { s[t][0]=s[t][1]=qq[t][0]=qq[t][1]=0.f; }

#pragma unroll
        for (int j = 0; j < 16; j++) {
            int col = j * 8 + 2 * t4;
            float2 bb = __ldg((const float2*)(bias + col));
#pragma unroll
            for (int t = 0; t < 2; t++) {
                c[t][j][0] += bb.x; c[t][j][1] += bb.y;
                c[t][j][2] += bb.x; c[t][j][3] += bb.y;
                s[t][0]  += c[t][j][0] + c[t][j][1];
                qq[t][0] += c[t][j][0] * c[t][j][0] + c[t][j][1] * c[t][j][1];
                s[t][1]  += c[t][j][2] + c[t][j][3];
                qq[t][1] += c[t][j][2] * c[t][j][2] + c[t][j][3] * c[t][j][3];
            }
        }
#pragma unroll
        for (int o = 1; o <= 2; o <<= 1) {
#pragma unroll
            for (int t = 0; t < 2; t++) {
                s[t][0]  += __shfl_xor_sync(0xFFFFFFFFu, s[t][0], o);
                qq[t][0] += __shfl_xor_sync(0xFFFFFFFFu, qq[t][0], o);
                s[t][1]  += __shfl_xor_sync(0xFFFFFFFFu, s[t][1], o);
                qq[t][1] += __shfl_xor_sync(0xFFFFFFFFu, qq[t][1], o);
            }
        }
        float mean[2][2], rstd[2][2];
#pragma unroll
        for (int t = 0; t < 2; t++)
#pragma unroll
            for (int h = 0; h < 2; h++) {
                mean[t][h] = s[t][h] * (1.f / 128.f);
                rstd[t][h] = rsqrtf(qq[t][h] * (1.f / 128.f) - mean[t][h] * mean[t][h] + 1e-5f);
            }

        if (l == 3) {
#pragma unroll
            for (int j = 0; j < 16; j++) {
                int col = j * 8 + 2 * t4;
                float2 gg = __ldg((const float2*)(gamma + col));
                float2 ee = __ldg((const float2*)(beta + col));
#pragma unroll
                for (int t = 0; t < 2; t++) {
                    int ra = row0 + t * 16 + g;
                    int rb = ra + 8;
                    if (ra < NN) {
                        float2 o1;
                        o1.x = fast_tanh((c[t][j][0] - mean[t][0]) * rstd[t][0] * gg.x + ee.x);
                        o1.y = fast_tanh((c[t][j][1] - mean[t][0]) * rstd[t][0] * gg.y + ee.y);
                        *(float2*)(out + (size_t)ra * DD + col) = o1;
                    }
                    if (rb < NN) {
                        float2 o2;
                        o2.x = fast_tanh((c[t][j][2] - mean[t][1]) * rstd[t][1] * gg.x + ee.x);
                        o2.y = fast_tanh((c[t][j][3] - mean[t][1]) * rstd[t][1] * gg.y + ee.y);
                        *(float2*)(out + (size_t)rb * DD + col) = o2;
                    }
                }
            }
            break;
        }

        // Write h (half2) into per-warp smem slab. Col pair (2t4, 2t4+1) is one uint32.
        __syncwarp();
#pragma unroll
        for (int j = 0; j < 16; j++) {
            int col = j * 8 + 2 * t4;
            float2 gg = __ldg((const float2*)(gamma + col));
            float2 ee = __ldg((const float2*)(beta + col));
            int ci = j * 4 + t4;    // uint32 column index
#pragma unroll
            for (int t = 0; t < 2; t++) {
                float h00 = fast_tanh((c[t][j][0] - mean[t][0]) * rstd[t][0] * gg.x + ee.x);
                float h01 = fast_tanh((c[t][j][1] - mean[t][0]) * rstd[t][0] * gg.y + ee.y);
                float h10 = fast_tanh((c[t][j][2] - mean[t][1]) * rstd[t][1] * gg.x + ee.x);
                float h11 = fast_tanh((c[t][j][3] - mean[t][1]) * rstd[t][1] * gg.y + ee.y);
                Hw[(t * 16 + g) * HS16 + ci]     = pack_h2(h00, h01);
                Hw[(t * 16 + g + 8) * HS16 + ci] = pack_h2(h10, h11);
                c[t][j][0] = 0.f; c[t][j][1] = 0.f;
                c[t][j][2] = 0.f; c[t][j][3] = 0.f;
            }
        }
        __syncwarp();

        // Next layer GEMM: h (in Hw) @ W[l], K = 128
#pragma unroll
        for (int kc = 0; kc < 4; kc++) {
            int chunk = 12 + l * 4 + kc;
#pragma unroll
            for (int s = 0; s < 2; s++) {
                int kidx = kc * 16 + s * 8 + t4;
                uint32_t a0[4], a1[4];
                a0[0] = Hw[(g) * HS16 + kidx];
                a0[1] = Hw[(g + 8) * HS16 + kidx];
                a0[2] = Hw[(g) * HS16 + kidx + 4];
                a0[3] = Hw[(g + 8) * HS16 + kidx + 4];
                a1[0] = Hw[(16 + g) * HS16 + kidx];
                a1[1] = Hw[(24 + g) * HS16 + kidx];
                a1[2] = Hw[(16 + g) * HS16 + kidx + 4];
                a1[3] = Hw[(24 + g) * HS16 + kidx + 4];
                const uint4* wfk = WF + ((size_t)(chunk * 2 + s) << 8);
#pragma unroll
                for (int q = 0; q < 8; q++) {
                    uint4 bb = __ldg(&wfk[(q << 5) + lane]);
                    MMA16(c[0][2 * q],     a0[0], a0[1], a0[2], a0[3], bb.x, bb.y);
                    MMA16(c[0][2 * q + 1], a0[0], a0[1], a0[2], a0[3], bb.z, bb.w);
                    MMA16(c[1][2 * q],     a1[0], a1[1], a1[2], a1[3], bb.x, bb.y);
                    MMA16(c[1][2 * q + 1], a1[0], a1[1], a1[2], a1[3], bb.z, bb.w);
                }
            }
        }
    }
}

// ---------------------------------------------------------------------------
extern "C" void kernel_launch(void* const* d_in, const int* in_sizes, int n_in,
                              void* d_out, int out_size) {
    const float* x   = (const float*)d_in[0];
    const float* e   = (const float*)d_in[1];
    const int*   ei  = (const int*)d_in[2];
    const float* W0  = (const float*)d_in[3];
    const float* b0  = (const float*)d_in[4];
    const float* g0  = (const float*)d_in[5];
    const float* be0 = (const float*)d_in[6];
    const float* W   = (const float*)d_in[7];
    const float* b   = (const float*)d_in[8];
    const float* g   = (const float*)d_in[9];
    const float* be  = (const float*)d_in[10];
    float* out = (float*)d_out;

    uint32_t *xh, *mih, *moh;
    int *cnt, *offin, *offout, *curin, *curout;
    int2 *lin, *lout;
    uint4* wf;
    cudaGetSymbolAddress((void**)&xh, g_xh);
    cudaGetSymbolAddress((void**)&mih, g_mih);
    cudaGetSymbolAddress((void**)&moh, g_moh);
    cudaGetSymbolAddress((void**)&cnt, g_cnt);
    cudaGetSymbolAddress((void**)&offin, g_off_in);
    cudaGetSymbolAddress((void**)&offout, g_off_out);
    cudaGetSymbolAddress((void**)&curin, g_cur_in);
    cudaGetSymbolAddress((void**)&curout, g_cur_out);
    cudaGetSymbolAddress((void**)&lin, g_lst_in);
    cudaGetSymbolAddress((void**)&lout, g_lst_out);
    cudaGetSymbolAddress((void**)&wf, g_wfrag);
    int* cursors = cnt + 2 * NN;

    const int smem_bytes = 4 * 32 * HS16 * 4;   // 4 warps x 32 rows x 68 words
    cudaFuncSetAttribute(mlp_fused,
                         cudaFuncAttributeMaxDynamicSharedMemorySize,
                         smem_bytes);

    cudaMemsetAsync(cnt, 0, (2 * NN + 2) * sizeof(int));

    prep_kernel<<<PREP_BLOCKS, 256>>>(x, xh, W0, W, wf, ei, cnt);
    alloc_kernel<<<(2 * NN + 255) / 256, 256>>>(cnt, offin, curin, offout, curout, cursors);
    fill_kernel<<<(NE / 16 + 255) / 256, 256>>>(ei, e, curin, curout, lin, lout);

    {
        long long warps = 2LL * NN;
        int blocks = (int)((warps * 32 + 255) / 256);
        gather_kernel<<<blocks, 256>>>(xh, cnt, offin, lin, offout, lout, mih, moh);
    }

    const int gblocks = (NN + ROWS_PER_BLOCK - 1) / ROWS_PER_BLOCK;  // 782
    mlp_fused<<<gblocks, MLP_THREADS, smem_bytes>>>(
        mih, moh, xh, wf, b0, g0, be0, b, g, be, out);
}

// round 14
// speedup vs baseline: 1.2352x; 1.1048x over previous
#include <cuda_runtime.h>
#include <cuda_fp16.h>
#include <math.h>
#include <stdint.h>

#define NN 100000
#define DD 128
#define NE 1600000

#define MLP_THREADS 256          // 8 warps; each warp owns 16 rows
#define ROWS_PER_BLOCK 128
#define N_CHUNKS 24              // 12 layer-0 (384 k) + 12 inner (3 x 128 k)
#define HS16 68                  // H slab row stride in uint32 (half2) units

// prep_kernel block ranges
#define PREP_XCONV_BLOCKS 12500  // NN*128/4 float4s / 256 threads
#define PREP_WFRAG_BLOCKS 48     // N_CHUNKS*512/256
#define PREP_HIST_BLOCKS  782    // ceil(NE/8/256)
#define PREP_BLOCKS (PREP_XCONV_BLOCKS + PREP_WFRAG_BLOCKS + PREP_HIST_BLOCKS)

// Scratch (allocation-free rule: __device__ globals)
__device__ uint32_t g_xh[(size_t)NN * 64];    // x as half2 pairs (plain layout)
__device__ uint32_t g_mih[(size_t)NN * 64];
__device__ uint32_t g_moh[(size_t)NN * 64];

__device__ int   g_cnt[2 * NN + 2];   // [2NN..2NN+2): global cursors
__device__ int   g_off_in[NN];
__device__ int   g_off_out[NN];
__device__ int   g_cur_in[NN];
__device__ int   g_cur_out[NN];
__device__ int2  g_lst_in[NE];
__device__ int2  g_lst_out[NE];
__device__ uint4 g_wfrag[N_CHUNKS * 2 * 8 * 32];   // fp16 frag-major weights

// ---------------------------------------------------------------------------
__device__ __forceinline__ float fast_tanh(float x) {
    float ax = fabsf(x);
    float t = __expf(-2.f * ax);
    float r = (1.f - t) * __frcp_rn(1.f + t);
    return copysignf(r, x);
}

__device__ __forceinline__ uint32_t pack_h2(float a, float b) {
    __half2 h = __floats2half2_rn(a, b);
    return *(uint32_t*)&h;
}

// ---------------------------------------------------------------------------
// Fused prep: xconv (blocks [0,12500)), wfrag (next 48), hist (last 782).
// ---------------------------------------------------------------------------
__global__ void prep_kernel(const float* __restrict__ x, uint32_t* __restrict__ xh,
                            const float* __restrict__ W0, const float* __restrict__ W,
                            uint4* __restrict__ WF,
                            const int* __restrict__ ei, int* __restrict__ cnt) {
    int b = blockIdx.x;
    if (b < PREP_XCONV_BLOCKS) {
        int i = b * 256 + threadIdx.x;
        float4 v = __ldg((const float4*)x + i);
        uint2 o;
        o.x = pack_h2(v.x, v.y);
        o.y = pack_h2(v.z, v.w);
        ((uint2*)xh)[i] = o;
        return;
    }
    b -= PREP_XCONV_BLOCKS;
    if (b < PREP_WFRAG_BLOCKS) {
        int idx = b * 256 + threadIdx.x;
        int lane = idx & 31;
        int q = (idx >> 5) & 7;
        int s = (idx >> 8) & 1;
        int chunk = idx >> 9;
        int t4 = lane & 3, g = lane >> 2;

        const float* Wsrc;
        int kbase;
        if (chunk < 12) {
            Wsrc = W0;
            kbase = chunk * 32;
        } else {
            int c2 = chunk - 12;
            Wsrc = W + (size_t)(c2 >> 2) * 128 * 128;
            kbase = (c2 & 3) * 32;
        }
        int k0 = kbase + s * 16 + 2 * t4;
        int n0 = (2 * q) * 8 + g;
        int n1 = n0 + 8;

        uint4 o;
        o.x = pack_h2(__ldg(&Wsrc[(size_t)k0 * 128 + n0]),       __ldg(&Wsrc[(size_t)(k0 + 1) * 128 + n0]));
        o.y = pack_h2(__ldg(&Wsrc[(size_t)(k0 + 8) * 128 + n0]), __ldg(&Wsrc[(size_t)(k0 + 9) * 128 + n0]));
        o.z = pack_h2(__ldg(&Wsrc[(size_t)k0 * 128 + n1]),       __ldg(&Wsrc[(size_t)(k0 + 1) * 128 + n1]));
        o.w = pack_h2(__ldg(&Wsrc[(size_t)(k0 + 8) * 128 + n1]), __ldg(&Wsrc[(size_t)(k0 + 9) * 128 + n1]));
        WF[idx] = o;
        return;
    }
    b -= PREP_WFRAG_BLOCKS;
    {
        int i = b * 256 + threadIdx.x;
        if (i >= NE / 8) return;
        int4 s0 = __ldg((const int4*)ei + 2 * i);
        int4 s1 = __ldg((const int4*)ei + 2 * i + 1);
        int4 t0 = __ldg((const int4*)(ei + NE) + 2 * i);
        int4 t1 = __ldg((const int4*)(ei + NE) + 2 * i + 1);
        atomicAdd(&cnt[t0.x], 1); atomicAdd(&cnt[t0.y], 1);
        atomicAdd(&cnt[t0.z], 1); atomicAdd(&cnt[t0.w], 1);
        atomicAdd(&cnt[t1.x], 1); atomicAdd(&cnt[t1.y], 1);
        atomicAdd(&cnt[t1.z], 1); atomicAdd(&cnt[t1.w], 1);
        atomicAdd(&cnt[NN + s0.x], 1); atomicAdd(&cnt[NN + s0.y], 1);
        atomicAdd(&cnt[NN + s0.z], 1); atomicAdd(&cnt[NN + s0.w], 1);
        atomicAdd(&cnt[NN + s1.x], 1); atomicAdd(&cnt[NN + s1.y], 1);
        atomicAdd(&cnt[NN + s1.z], 1); atomicAdd(&cnt[NN + s1.w], 1);
    }
}

// ---------------------------------------------------------------------------
// Parallel segment allocation (offsets unordered)
// ---------------------------------------------------------------------------
__global__ void alloc_kernel(const int* __restrict__ cnt,
                             int* __restrict__ offin, int* __restrict__ curin,
                             int* __restrict__ offout, int* __restrict__ curout,
                             int* __restrict__ cursors) {
    int i = blockIdx.x * blockDim.x + threadIdx.x;
    if (i >= 2 * NN) return;
    int lane = threadIdx.x & 31;
    int c = cnt[i];
    int inc = c;
#pragma unroll
    for (int o = 1; o < 32; o <<= 1) {
        int v = __shfl_up_sync(0xFFFFFFFFu, inc, o);
        if (lane >= o) inc += v;
    }
    int tot = __shfl_sync(0xFFFFFFFFu, inc, 31);
    int ex = inc - c;
    int half = (i < NN) ? 0 : 1;
    int base = 0;
    if (lane == 0) base = atomicAdd(&cursors[half], tot);
    base = __shfl_sync(0xFFFFFFFFu, base, 0);
    int off = base + ex;
    if (half == 0) { offin[i] = off; curin[i] = off; }
    else           { offout[i - NN] = off; curout[i - NN] = off; }
}

// ---------------------------------------------------------------------------
// Fill CSR lists: 16 edges/thread, all atomics issued before stores (MLP)
// ---------------------------------------------------------------------------
__global__ void fill_kernel(const int* __restrict__ ei, const float* __restrict__ e,
                            int* __restrict__ curin, int* __restrict__ curout,
                            int2* __restrict__ lin, int2* __restrict__ lout) {
    int i = blockIdx.x * blockDim.x + threadIdx.x;
    if (i >= NE / 16) return;
    int ss[16], tt[16];
    float ww[16];
#pragma unroll
    for (int v4 = 0; v4 < 4; v4++) {
        int4 s = __ldg((const int4*)ei + 4 * i + v4);
        int4 t = __ldg((const int4*)(ei + NE) + 4 * i + v4);
        float4 w = __ldg((const float4*)e + 4 * i + v4);
        ss[4 * v4 + 0] = s.x; ss[4 * v4 + 1] = s.y; ss[4 * v4 + 2] = s.z; ss[4 * v4 + 3] = s.w;
        tt[4 * v4 + 0] = t.x; tt[4 * v4 + 1] = t.y; tt[4 * v4 + 2] = t.z; tt[4 * v4 + 3] = t.w;
        ww[4 * v4 + 0] = w.x; ww[4 * v4 + 1] = w.y; ww[4 * v4 + 2] = w.z; ww[4 * v4 + 3] = w.w;
    }
    int pin[16], pout[16];
#pragma unroll
    for (int u = 0; u < 16; u++) pin[u] = atomicAdd(&curin[tt[u]], 1);
#pragma unroll
    for (int u = 0; u < 16; u++) pout[u] = atomicAdd(&curout[ss[u]], 1);
#pragma unroll
    for (int u = 0; u < 16; u++) lin[pin[u]] = make_int2(ss[u], __float_as_int(ww[u]));
#pragma unroll
    for (int u = 0; u < 16; u++) lout[pout[u]] = make_int2(tt[u], __float_as_int(ww[u]));
}

// ---------------------------------------------------------------------------
// Gather (fp16): one warp per (node, dir), HALF-WARP EDGE PAIRING.
// Lanes 0-15 handle edge j, lanes 16-31 handle edge j+1; each lane reads a
// uint4 (8 fp16 cols). Halves merged via shfl_xor(16) at the end.
// ---------------------------------------------------------------------------
__global__ __launch_bounds__(256) void gather_kernel(
    const uint32_t* __restrict__ xh, const int* __restrict__ cnt,
    const int* __restrict__ offin, const int2* __restrict__ lin,
    const int* __restrict__ offout, const int2* __restrict__ lout,
    uint32_t* __restrict__ mih, uint32_t* __restrict__ moh) {
    int wg = (blockIdx.x * blockDim.x + threadIdx.x) >> 5;
    int lane = threadIdx.x & 31;
    if (wg >= 2 * NN) return;
    int half = lane >> 4;       // 0 or 1
    int sub = lane & 15;        // uint4 index within row

    const int* off;
    const int2* lst;
    uint32_t* dst;
    int node, cofs;
    if (wg < NN) { node = wg; off = offin; lst = lin; dst = mih; cofs = 0; }
    else         { node = wg - NN; off = offout; lst = lout; dst = moh; cofs = NN; }

    int beg = off[node];
    int end = beg + cnt[cofs + node];

    float2 a0 = make_float2(0.f, 0.f), a1 = make_float2(0.f, 0.f);
    float2 a2 = make_float2(0.f, 0.f), a3 = make_float2(0.f, 0.f);

    int j = beg;
    // 2 pairs (4 edges) per iteration
    for (; j + 4 <= end; j += 4) {
        int2 p0 = __ldg(&lst[j + half]);
        int2 p1 = __ldg(&lst[j + 2 + half]);
        uint4 v0 = __ldg((const uint4*)(xh + (size_t)p0.x * 64) + sub);
        uint4 v1 = __ldg((const uint4*)(xh + (size_t)p1.x * 64) + sub);
        float w0 = __int_as_float(p0.y);
        float w1 = __int_as_float(p1.y);
        float2 f;
        f = __half22float2(*(__half2*)&v0.x); a0.x = fmaf(w0, f.x, a0.x); a0.y = fmaf(w0, f.y, a0.y);
        f = __half22float2(*(__half2*)&v0.y); a1.x = fmaf(w0, f.x, a1.x); a1.y = fmaf(w0, f.y, a1.y);
        f = __half22float2(*(__half2*)&v0.z); a2.x = fmaf(w0, f.x, a2.x); a2.y = fmaf(w0, f.y, a2.y);
        f = __half22float2(*(__half2*)&v0.w); a3.x = fmaf(w0, f.x, a3.x); a3.y = fmaf(w0, f.y, a3.y);
        f = __half22float2(*(__half2*)&v1.x); a0.x = fmaf(w1, f.x, a0.x); a0.y = fmaf(w1, f.y, a0.y);
        f = __half22float2(*(__half2*)&v1.y); a1.x = fmaf(w1, f.x, a1.x); a1.y = fmaf(w1, f.y, a1.y);
        f = __half22float2(*(__half2*)&v1.z); a2.x = fmaf(w1, f.x, a2.x); a2.y = fmaf(w1, f.y, a2.y);
        f = __half22float2(*(__half2*)&v1.w); a3.x = fmaf(w1, f.x, a3.x); a3.y = fmaf(w1, f.y, a3.y);
    }
    // 1 pair
    for (; j + 2 <= end; j += 2) {
        int2 p0 = __ldg(&lst[j + half]);
        uint4 v0 = __ldg((const uint4*)(xh + (size_t)p0.x * 64) + sub);
        float w0 = __int_as_float(p0.y);
        float2 f;
        f = __half22float2(*(__half2*)&v0.x); a0.x = fmaf(w0, f.x, a0.x); a0.y = fmaf(w0, f.y, a0.y);
        f = __half22float2(*(__half2*)&v0.y); a1.x = fmaf(w0, f.x, a1.x); a1.y = fmaf(w0, f.y, a1.y);
        f = __half22float2(*(__half2*)&v0.z); a2.x = fmaf(w0, f.x, a2.x); a2.y = fmaf(w0, f.y, a2.y);
        f = __half22float2(*(__half2*)&v0.w); a3.x = fmaf(w0, f.x, a3.x); a3.y = fmaf(w0, f.y, a3.y);
    }
    // possible last single edge: half 0 only
    if (j < end && half == 0) {
        int2 p0 = __ldg(&lst[j]);
        uint4 v0 = __ldg((const uint4*)(xh + (size_t)p0.x * 64) + sub);
        float w0 = __int_as_float(p0.y);
        float2 f;
        f = __half22float2(*(__half2*)&v0.x); a0.x = fmaf(w0, f.x, a0.x); a0.y = fmaf(w0, f.y, a0.y);
        f = __half22float2(*(__half2*)&v0.y); a1.x = fmaf(w0, f.x, a1.x); a1.y = fmaf(w0, f.y, a1.y);
        f = __half22float2(*(__half2*)&v0.z); a2.x = fmaf(w0, f.x, a2.x); a2.y = fmaf(w0, f.y, a2.y);
        f = __half22float2(*(__half2*)&v0.w); a3.x = fmaf(w0, f.x, a3.x); a3.y = fmaf(w0, f.y, a3.y);
    }

    // merge halves
    a0.x += __shfl_xor_sync(0xFFFFFFFFu, a0.x, 16);
    a0.y += __shfl_xor_sync(0xFFFFFFFFu, a0.y, 16);
    a1.x += __shfl_xor_sync(0xFFFFFFFFu, a1.x, 16);
    a1.y += __shfl_xor_sync(0xFFFFFFFFu, a1.y, 16);
    a2.x += __shfl_xor_sync(0xFFFFFFFFu, a2.x, 16);
    a2.y += __shfl_xor_sync(0xFFFFFFFFu, a2.y, 16);
    a3.x += __shfl_xor_sync(0xFFFFFFFFu, a3.x, 16);
    a3.y += __shfl_xor_sync(0xFFFFFFFFu, a3.y, 16);

    if (half == 0) {
        uint4 o;
        o.x = pack_h2(a0.x, a0.y);
        o.y = pack_h2(a1.x, a1.y);
        o.z = pack_h2(a2.x, a2.y);
        o.w = pack_h2(a3.x, a3.y);
        ((uint4*)(dst + (size_t)node * 64))[sub] = o;
    }
}

// ---------------------------------------------------------------------------
// Fused 4-layer MLP, fp16 m16n8k16. 16 rows per warp (one m16 tile),
// 256 threads x 2 blocks/SM = 16 warps/SM for latency hiding.
// ---------------------------------------------------------------------------
#define MMA16(cj, A0r, A1r, A2r, A3r, B0r, B1r)                                  \
    asm volatile(                                                                \
        "mma.sync.aligned.m16n8k16.row.col.f32.f16.f16.f32 "                     \
        "{%0,%1,%2,%3}, {%4,%5,%6,%7}, {%8,%9}, {%0,%1,%2,%3};"                  \
        : "+f"(cj[0]), "+f"(cj[1]), "+f"(cj[2]), "+f"(cj[3])                     \
        : "r"(A0r), "r"(A1r), "r"(A2r), "r"(A3r), "r"(B0r), "r"(B1r))

__global__ __launch_bounds__(MLP_THREADS, 2) void mlp_fused(
    const uint32_t* __restrict__ A0h, const uint32_t* __restrict__ A1h,
    const uint32_t* __restrict__ A2h,
    const uint4* __restrict__ WF,
    const float* __restrict__ b0v, const float* __restrict__ g0v,
    const float* __restrict__ be0v,
    const float* __restrict__ bv, const float* __restrict__ gv,
    const float* __restrict__ bev,
    float* __restrict__ out)
{
    extern __shared__ uint32_t smem[];
    const int tid = threadIdx.x;
    const int lane = tid & 31;
    const int wid = tid >> 5;
    const int g = lane >> 2;
    const int t4 = lane & 3;
    const int row0 = blockIdx.x * ROWS_PER_BLOCK + wid * 16;

    uint32_t* Hw = smem + wid * 16 * HS16;   // per-warp slab [16][HS16] half2

    float c[16][4];
#pragma unroll
    for (int j = 0; j < 16; j++)
#pragma unroll
        for (int q = 0; q < 4; q++) c[j][q] = 0.f;

    int r00 = row0 + g;
    size_t cr00 = (size_t)(r00 < NN ? r00 : 0) * 64;
    size_t cr01 = (size_t)((r00 + 8) < NN ? (r00 + 8) : 0) * 64;

    // ---------------- Layer 0: K = 384 over {mih, moh, xh} ----------------
    const uint32_t* Ap[3] = {A0h, A1h, A2h};
#pragma unroll 1
    for (int m = 0; m < 3; m++) {
        const uint32_t* A = Ap[m];
#pragma unroll
        for (int kc = 0; kc < 4; kc++) {
            int chunk = m * 4 + kc;
#pragma unroll
            for (int s = 0; s < 2; s++) {
                int kidx = kc * 16 + s * 8 + t4;       // uint32 (half2) index
                uint32_t a0[4];
                a0[0] = __ldg(A + cr00 + kidx);
                a0[1] = __ldg(A + cr01 + kidx);
                a0[2] = __ldg(A + cr00 + kidx + 4);
                a0[3] = __ldg(A + cr01 + kidx + 4);
                const uint4* wfk = WF + ((size_t)(chunk * 2 + s) << 8);
#pragma unroll
                for (int q = 0; q < 8; q++) {
                    uint4 bb = __ldg(&wfk[(q << 5) + lane]);
                    MMA16(c[2 * q],     a0[0], a0[1], a0[2], a0[3], bb.x, bb.y);
                    MMA16(c[2 * q + 1], a0[0], a0[1], a0[2], a0[3], bb.z, bb.w);
                }
            }
        }
    }

    // ---------------- 4 epilogues + 3 inner layers ----------------
#pragma unroll 1
    for (int l = 0; l < 4; l++) {
        const float* bias  = (l == 0) ? b0v  : bv  + (l - 1) * 128;
        const float* gamma = (l == 0) ? g0v  : gv  + (l - 1) * 128;
        const float* beta  = (l == 0) ? be0v : bev + (l - 1) * 128;

        float s0 = 0.f, q0 = 0.f, s1 = 0.f, q1 = 0.f;
#pragma unroll
        for (int j = 0; j < 16; j++) {
            int col = j * 8 + 2 * t4;
            float2 bb = __ldg((const float2*)(bias + col));
            c[j][0] += bb.x; c[j][1] += bb.y;
            c[j][2] += bb.x; c[j][3] += bb.y;
            s0 += c[j][0] + c[j][1];
            q0 += c[j][0] * c[j][0] + c[j][1] * c[j][1];
            s1 += c[j][2] + c[j][3];
            q1 += c[j][2] * c[j][2] + c[j][3] * c[j][3];
        }
#pragma unroll
        for (int o = 1; o <= 2; o <<= 1) {
            s0 += __shfl_xor_sync(0xFFFFFFFFu, s0, o);
            q0 += __shfl_xor_sync(0xFFFFFFFFu, q0, o);
            s1 += __shfl_xor_sync(0xFFFFFFFFu, s1, o);
            q1 += __shfl_xor_sync(0xFFFFFFFFu, q1, o);
        }
        float mean0 = s0 * (1.f / 128.f);
        float rstd0 = rsqrtf(q0 * (1.f / 128.f) - mean0 * mean0 + 1e-5f);
        float mean1 = s1 * (1.f / 128.f);
        float rstd1 = rsqrtf(q1 * (1.f / 128.f) - mean1 * mean1 + 1e-5f);

        if (l == 3) {
            int ra = row0 + g;
            int rb = ra + 8;
#pragma unroll
            for (int j = 0; j < 16; j++) {
                int col = j * 8 + 2 * t4;
                float2 gg = __ldg((const float2*)(gamma + col));
                float2 ee = __ldg((const float2*)(beta + col));
                if (ra < NN) {
                    float2 o1;
                    o1.x = fast_tanh((c[j][0] - mean0) * rstd0 * gg.x + ee.x);
                    o1.y = fast_tanh((c[j][1] - mean0) * rstd0 * gg.y + ee.y);
                    *(float2*)(out + (size_t)ra * DD + col) = o1;
                }
                if (rb < NN) {
                    float2 o2;
                    o2.x = fast_tanh((c[j][2] - mean1) * rstd1 * gg.x + ee.x);
                    o2.y = fast_tanh((c[j][3] - mean1) * rstd1 * gg.y + ee.y);
                    *(float2*)(out + (size_t)rb * DD + col) = o2;
                }
            }
            break;
        }

        // Write h (half2) into per-warp smem slab.
        __syncwarp();
#pragma unroll
        for (int j = 0; j < 16; j++) {
            int col = j * 8 + 2 * t4;
            float2 gg = __ldg((const float2*)(gamma + col));
            float2 ee = __ldg((const float2*)(beta + col));
            int ci = j * 4 + t4;
            float h00 = fast_tanh((c[j][0] - mean0) * rstd0 * gg.x + ee.x);
            float h01 = fast_tanh((c[j][1] - mean0) * rstd0 * gg.y + ee.y);
            float h10 = fast_tanh((c[j][2] - mean1) * rstd1 * gg.x + ee.x);
            float h11 = fast_tanh((c[j][3] - mean1) * rstd1 * gg.y + ee.y);
            Hw[(g) * HS16 + ci]     = pack_h2(h00, h01);
            Hw[(g + 8) * HS16 + ci] = pack_h2(h10, h11);
            c[j][0] = 0.f; c[j][1] = 0.f;
            c[j][2] = 0.f; c[j][3] = 0.f;
        }
        __syncwarp();

        // Next layer GEMM: h (in Hw) @ W[l], K = 128
#pragma unroll
        for (int kc = 0; kc < 4; kc++) {
            int chunk = 12 + l * 4 + kc;
#pragma unroll
            for (int s = 0; s < 2; s++) {
                int kidx = kc * 16 + s * 8 + t4;
                uint32_t a0[4];
                a0[0] = Hw[(g) * HS16 + kidx];
                a0[1] = Hw[(g + 8) * HS16 + kidx];
                a0[2] = Hw[(g) * HS16 + kidx + 4];
                a0[3] = Hw[(g + 8) * HS16 + kidx + 4];
                const uint4* wfk = WF + ((size_t)(chunk * 2 + s) << 8);
#pragma unroll
                for (int q = 0; q < 8; q++) {
                    uint4 bb = __ldg(&wfk[(q << 5) + lane]);
                    MMA16(c[2 * q],     a0[0], a0[1], a0[2], a0[3], bb.x, bb.y);
                    MMA16(c[2 * q + 1], a0[0], a0[1], a0[2], a0[3], bb.z, bb.w);
                }
            }
        }
    }
}

// ---------------------------------------------------------------------------
extern "C" void kernel_launch(void* const* d_in, const int* in_sizes, int n_in,
                              void* d_out, int out_size) {
    const float* x   = (const float*)d_in[0];
    const float* e   = (const float*)d_in[1];
    const int*   ei  = (const int*)d_in[2];
    const float* W0  = (const float*)d_in[3];
    const float* b0  = (const float*)d_in[4];
    const float* g0  = (const float*)d_in[5];
    const float* be0 = (const float*)d_in[6];
    const float* W   = (const float*)d_in[7];
    const float* b   = (const float*)d_in[8];
    const float* g   = (const float*)d_in[9];
    const float* be  = (const float*)d_in[10];
    float* out = (float*)d_out;

    uint32_t *xh, *mih, *moh;
    int *cnt, *offin, *offout, *curin, *curout;
    int2 *lin, *lout;
    uint4* wf;
    cudaGetSymbolAddress((void**)&xh, g_xh);
    cudaGetSymbolAddress((void**)&mih, g_mih);
    cudaGetSymbolAddress((void**)&moh, g_moh);
    cudaGetSymbolAddress((void**)&cnt, g_cnt);
    cudaGetSymbolAddress((void**)&offin, g_off_in);
    cudaGetSymbolAddress((void**)&offout, g_off_out);
    cudaGetSymbolAddress((void**)&curin, g_cur_in);
    cudaGetSymbolAddress((void**)&curout, g_cur_out);
    cudaGetSymbolAddress((void**)&lin, g_lst_in);
    cudaGetSymbolAddress((void**)&lout, g_lst_out);
    cudaGetSymbolAddress((void**)&wf, g_wfrag);
    int* cursors = cnt + 2 * NN;

    const int smem_bytes = 8 * 16 * HS16 * 4;   // 8 warps x 16 rows x 68 words
    cudaFuncSetAttribute(mlp_fused,
                         cudaFuncAttributeMaxDynamicSharedMemorySize,
                         smem_bytes);

    cudaMemsetAsync(cnt, 0, (2 * NN + 2) * sizeof(int));

    prep_kernel<<<PREP_BLOCKS, 256>>>(x, xh, W0, W, wf, ei, cnt);
    alloc_kernel<<<(2 * NN + 255) / 256, 256>>>(cnt, offin, curin, offout, curout, cursors);
    fill_kernel<<<(NE / 16 + 255) / 256, 256>>>(ei, e, curin, curout, lin, lout);

    {
        long long warps = 2LL * NN;
        int blocks = (int)((warps * 32 + 255) / 256);
        gather_kernel<<<blocks, 256>>>(xh, cnt, offin, lin, offout, lout, mih, moh);
    }

    const int gblocks = (NN + ROWS_PER_BLOCK - 1) / ROWS_PER_BLOCK;  // 782
    mlp_fused<<<gblocks, MLP_THREADS, smem_bytes>>>(
        mih, moh, xh, wf, b0, g0, be0, b, g, be, out);
}

// round 15
// speedup vs baseline: 1.3043x; 1.0559x over previous
#include <cuda_runtime.h>
#include <cuda_fp16.h>
#include <math.h>
#include <stdint.h>

#define NN 100000
#define DD 128
#define NE 1600000

#define MLP_THREADS 256          // 8 warps; each warp owns 16 rows
#define ROWS_PER_BLOCK 128
#define N_CHUNKS 24              // 12 layer-0 (384 k) + 12 inner (3 x 128 k)
#define HS16 68                  // H slab row stride in uint32 (half2) units

// prep_kernel block ranges
#define PREP_XCONV_BLOCKS 12500  // NN*128/4 float4s / 256 threads
#define PREP_WFRAG_BLOCKS 48     // N_CHUNKS*512/256
#define PREP_HIST_BLOCKS  782    // ceil(NE/8/256)
#define PREP_BLOCKS (PREP_XCONV_BLOCKS + PREP_WFRAG_BLOCKS + PREP_HIST_BLOCKS)

// Scratch (allocation-free rule: __device__ globals)
__device__ uint32_t g_xh[(size_t)NN * 64];    // x as half2 pairs (plain layout)
__device__ uint32_t g_mih[(size_t)NN * 64];
__device__ uint32_t g_moh[(size_t)NN * 64];

__device__ int   g_cnt[2 * NN + 2];   // [2NN..2NN+2): global cursors
__device__ int   g_off_in[NN];
__device__ int   g_off_out[NN];
__device__ int   g_cur_in[NN];
__device__ int   g_cur_out[NN];
__device__ int2  g_lst_in[NE];
__device__ int2  g_lst_out[NE];
__device__ uint4 g_wfrag[N_CHUNKS * 2 * 8 * 32];   // fp16 frag-major weights

// ---------------------------------------------------------------------------
__device__ __forceinline__ float fast_tanh(float x) {
    float ax = fabsf(x);
    float t = __expf(-2.f * ax);
    float r = (1.f - t) * __frcp_rn(1.f + t);
    return copysignf(r, x);
}

__device__ __forceinline__ uint32_t pack_h2(float a, float b) {
    __half2 h = __floats2half2_rn(a, b);
    return *(uint32_t*)&h;
}

// ---------------------------------------------------------------------------
// Fused prep: xconv (blocks [0,12500)), wfrag (next 48), hist (last 782).
// ---------------------------------------------------------------------------
__global__ void prep_kernel(const float* __restrict__ x, uint32_t* __restrict__ xh,
                            const float* __restrict__ W0, const float* __restrict__ W,
                            uint4* __restrict__ WF,
                            const int* __restrict__ ei, int* __restrict__ cnt) {
    int b = blockIdx.x;
    if (b < PREP_XCONV_BLOCKS) {
        int i = b * 256 + threadIdx.x;
        float4 v = __ldg((const float4*)x + i);
        uint2 o;
        o.x = pack_h2(v.x, v.y);
        o.y = pack_h2(v.z, v.w);
        ((uint2*)xh)[i] = o;
        return;
    }
    b -= PREP_XCONV_BLOCKS;
    if (b < PREP_WFRAG_BLOCKS) {
        int idx = b * 256 + threadIdx.x;
        int lane = idx & 31;
        int q = (idx >> 5) & 7;
        int s = (idx >> 8) & 1;
        int chunk = idx >> 9;
        int t4 = lane & 3, g = lane >> 2;

        const float* Wsrc;
        int kbase;
        if (chunk < 12) {
            Wsrc = W0;
            kbase = chunk * 32;
        } else {
            int c2 = chunk - 12;
            Wsrc = W + (size_t)(c2 >> 2) * 128 * 128;
            kbase = (c2 & 3) * 32;
        }
        int k0 = kbase + s * 16 + 2 * t4;
        int n0 = (2 * q) * 8 + g;
        int n1 = n0 + 8;

        uint4 o;
        o.x = pack_h2(__ldg(&Wsrc[(size_t)k0 * 128 + n0]),       __ldg(&Wsrc[(size_t)(k0 + 1) * 128 + n0]));
        o.y = pack_h2(__ldg(&Wsrc[(size_t)(k0 + 8) * 128 + n0]), __ldg(&Wsrc[(size_t)(k0 + 9) * 128 + n0]));
        o.z = pack_h2(__ldg(&Wsrc[(size_t)k0 * 128 + n1]),       __ldg(&Wsrc[(size_t)(k0 + 1) * 128 + n1]));
        o.w = pack_h2(__ldg(&Wsrc[(size_t)(k0 + 8) * 128 + n1]), __ldg(&Wsrc[(size_t)(k0 + 9) * 128 + n1]));
        WF[idx] = o;
        return;
    }
    b -= PREP_WFRAG_BLOCKS;
    {
        int i = b * 256 + threadIdx.x;
        if (i >= NE / 8) return;
        int4 s0 = __ldg((const int4*)ei + 2 * i);
        int4 s1 = __ldg((const int4*)ei + 2 * i + 1);
        int4 t0 = __ldg((const int4*)(ei + NE) + 2 * i);
        int4 t1 = __ldg((const int4*)(ei + NE) + 2 * i + 1);
        atomicAdd(&cnt[t0.x], 1); atomicAdd(&cnt[t0.y], 1);
        atomicAdd(&cnt[t0.z], 1); atomicAdd(&cnt[t0.w], 1);
        atomicAdd(&cnt[t1.x], 1); atomicAdd(&cnt[t1.y], 1);
        atomicAdd(&cnt[t1.z], 1); atomicAdd(&cnt[t1.w], 1);
        atomicAdd(&cnt[NN + s0.x], 1); atomicAdd(&cnt[NN + s0.y], 1);
        atomicAdd(&cnt[NN + s0.z], 1); atomicAdd(&cnt[NN + s0.w], 1);
        atomicAdd(&cnt[NN + s1.x], 1); atomicAdd(&cnt[NN + s1.y], 1);
        atomicAdd(&cnt[NN + s1.z], 1); atomicAdd(&cnt[NN + s1.w], 1);
    }
}

// ---------------------------------------------------------------------------
// Parallel segment allocation (offsets unordered)
// ---------------------------------------------------------------------------
__global__ void alloc_kernel(const int* __restrict__ cnt,
                             int* __restrict__ offin, int* __restrict__ curin,
                             int* __restrict__ offout, int* __restrict__ curout,
                             int* __restrict__ cursors) {
    int i = blockIdx.x * blockDim.x + threadIdx.x;
    if (i >= 2 * NN) return;
    int lane = threadIdx.x & 31;
    int c = cnt[i];
    int inc = c;
#pragma unroll
    for (int o = 1; o < 32; o <<= 1) {
        int v = __shfl_up_sync(0xFFFFFFFFu, inc, o);
        if (lane >= o) inc += v;
    }
    int tot = __shfl_sync(0xFFFFFFFFu, inc, 31);
    int ex = inc - c;
    int half = (i < NN) ? 0 : 1;
    int base = 0;
    if (lane == 0) base = atomicAdd(&cursors[half], tot);
    base = __shfl_sync(0xFFFFFFFFu, base, 0);
    int off = base + ex;
    if (half == 0) { offin[i] = off; curin[i] = off; }
    else           { offout[i - NN] = off; curout[i - NN] = off; }
}

// ---------------------------------------------------------------------------
// Fill CSR lists: 16 edges/thread, all atomics issued before stores (MLP)
// ---------------------------------------------------------------------------
__global__ void fill_kernel(const int* __restrict__ ei, const float* __restrict__ e,
                            int* __restrict__ curin, int* __restrict__ curout,
                            int2* __restrict__ lin, int2* __restrict__ lout) {
    int i = blockIdx.x * blockDim.x + threadIdx.x;
    if (i >= NE / 16) return;
    int ss[16], tt[16];
    float ww[16];
#pragma unroll
    for (int v4 = 0; v4 < 4; v4++) {
        int4 s = __ldg((const int4*)ei + 4 * i + v4);
        int4 t = __ldg((const int4*)(ei + NE) + 4 * i + v4);
        float4 w = __ldg((const float4*)e + 4 * i + v4);
        ss[4 * v4 + 0] = s.x; ss[4 * v4 + 1] = s.y; ss[4 * v4 + 2] = s.z; ss[4 * v4 + 3] = s.w;
        tt[4 * v4 + 0] = t.x; tt[4 * v4 + 1] = t.y; tt[4 * v4 + 2] = t.z; tt[4 * v4 + 3] = t.w;
        ww[4 * v4 + 0] = w.x; ww[4 * v4 + 1] = w.y; ww[4 * v4 + 2] = w.z; ww[4 * v4 + 3] = w.w;
    }
    int pin[16], pout[16];
#pragma unroll
    for (int u = 0; u < 16; u++) pin[u] = atomicAdd(&curin[tt[u]], 1);
#pragma unroll
    for (int u = 0; u < 16; u++) pout[u] = atomicAdd(&curout[ss[u]], 1);
#pragma unroll
    for (int u = 0; u < 16; u++) lin[pin[u]] = make_int2(ss[u], __float_as_int(ww[u]));
#pragma unroll
    for (int u = 0; u < 16; u++) lout[pout[u]] = make_int2(tt[u], __float_as_int(ww[u]));
}

// ---------------------------------------------------------------------------
// Gather (fp16): one warp per (node, dir). Round-13 version (97 us measured).
// ---------------------------------------------------------------------------
__global__ __launch_bounds__(256) void gather_kernel(
    const uint32_t* __restrict__ xh, const int* __restrict__ cnt,
    const int* __restrict__ offin, const int2* __restrict__ lin,
    const int* __restrict__ offout, const int2* __restrict__ lout,
    uint32_t* __restrict__ mih, uint32_t* __restrict__ moh) {
    int wg = (blockIdx.x * blockDim.x + threadIdx.x) >> 5;
    int lane = threadIdx.x & 31;
    if (wg >= 2 * NN) return;

    const int* off;
    const int2* lst;
    uint32_t* dst;
    int node, cofs;
    if (wg < NN) { node = wg; off = offin; lst = lin; dst = mih; cofs = 0; }
    else         { node = wg - NN; off = offout; lst = lout; dst = moh; cofs = NN; }

    int beg = off[node];
    int end = beg + cnt[cofs + node];

    float2 acc0 = make_float2(0.f, 0.f);
    float2 acc1 = make_float2(0.f, 0.f);

    int j = beg;
    for (; j + 8 <= end; j += 8) {
        int2 p[8];
#pragma unroll
        for (int u = 0; u < 8; u++) p[u] = __ldg(&lst[j + u]);
        uint2 v[8];
#pragma unroll
        for (int u = 0; u < 8; u++)
            v[u] = __ldg((const uint2*)(xh + (size_t)p[u].x * 64) + lane);
#pragma unroll
        for (int u = 0; u < 8; u++) {
            float w = __int_as_float(p[u].y);
            float2 f0 = __half22float2(*(__half2*)&v[u].x);
            float2 f1 = __half22float2(*(__half2*)&v[u].y);
            acc0.x = fmaf(w, f0.x, acc0.x); acc0.y = fmaf(w, f0.y, acc0.y);
            acc1.x = fmaf(w, f1.x, acc1.x); acc1.y = fmaf(w, f1.y, acc1.y);
        }
    }
    for (; j < end; j++) {
        int2 p0 = __ldg(&lst[j]);
        uint2 v0 = __ldg((const uint2*)(xh + (size_t)p0.x * 64) + lane);
        float w = __int_as_float(p0.y);
        float2 f0 = __half22float2(*(__half2*)&v0.x);
        float2 f1 = __half22float2(*(__half2*)&v0.y);
        acc0.x = fmaf(w, f0.x, acc0.x); acc0.y = fmaf(w, f0.y, acc0.y);
        acc1.x = fmaf(w, f1.x, acc1.x); acc1.y = fmaf(w, f1.y, acc1.y);
    }

    uint2 o;
    o.x = pack_h2(acc0.x, acc0.y);
    o.y = pack_h2(acc1.x, acc1.y);
    ((uint2*)(dst + (size_t)node * 64))[lane] = o;
}

// ---------------------------------------------------------------------------
// Fused 4-layer MLP, fp16 m16n8k16. 16 rows per warp (one m16 tile),
// 256 threads x 2 blocks/SM = 16 warps/SM for latency hiding. (Round-14 WIN.)
// ---------------------------------------------------------------------------
#define MMA16(cj, A0r, A1r, A2r, A3r, B0r, B1r)                                  \
    asm volatile(                                                                \
        "mma.sync.aligned.m16n8k16.row.col.f32.f16.f16.f32 "                     \
        "{%0,%1,%2,%3}, {%4,%5,%6,%7}, {%8,%9}, {%0,%1,%2,%3};"                  \
        : "+f"(cj[0]), "+f"(cj[1]), "+f"(cj[2]), "+f"(cj[3])                     \
        : "r"(A0r), "r"(A1r), "r"(A2r), "r"(A3r), "r"(B0r), "r"(B1r))

__global__ __launch_bounds__(MLP_THREADS, 2) void mlp_fused(
    const uint32_t* __restrict__ A0h, const uint32_t* __restrict__ A1h,
    const uint32_t* __restrict__ A2h,
    const uint4* __restrict__ WF,
    const float* __restrict__ b0v, const float* __restrict__ g0v,
    const float* __restrict__ be0v,
    const float* __restrict__ bv, const float* __restrict__ gv,
    const float* __restrict__ bev,
    float* __restrict__ out)
{
    extern __shared__ uint32_t smem[];
    const int tid = threadIdx.x;
    const int lane = tid & 31;
    const int wid = tid >> 5;
    const int g = lane >> 2;
    const int t4 = lane & 3;
    const int row0 = blockIdx.x * ROWS_PER_BLOCK + wid * 16;

    uint32_t* Hw = smem + wid * 16 * HS16;   // per-warp slab [16][HS16] half2

    float c[16][4];
#pragma unroll
    for (int j = 0; j < 16; j++)
#pragma unroll
        for (int q = 0; q < 4; q++) c[j][q] = 0.f;

    int r00 = row0 + g;
    size_t cr00 = (size_t)(r00 < NN ? r00 : 0) * 64;
    size_t cr01 = (size_t)((r00 + 8) < NN ? (r00 + 8) : 0) * 64;

    // ---------------- Layer 0: K = 384 over {mih, moh, xh} ----------------
    const uint32_t* Ap[3] = {A0h, A1h, A2h};
#pragma unroll 1
    for (int m = 0; m < 3; m++) {
        const uint32_t* A = Ap[m];
#pragma unroll
        for (int kc = 0; kc < 4; kc++) {
            int chunk = m * 4 + kc;
#pragma unroll
            for (int s = 0; s < 2; s++) {
                int kidx = kc * 16 + s * 8 + t4;       // uint32 (half2) index
                uint32_t a0[4];
                a0[0] = __ldg(A + cr00 + kidx);
                a0[1] = __ldg(A + cr01 + kidx);
                a0[2] = __ldg(A + cr00 + kidx + 4);
                a0[3] = __ldg(A + cr01 + kidx + 4);
                const uint4* wfk = WF + ((size_t)(chunk * 2 + s) << 8);
#pragma unroll
                for (int q = 0; q < 8; q++) {
                    uint4 bb = __ldg(&wfk[(q << 5) + lane]);
                    MMA16(c[2 * q],     a0[0], a0[1], a0[2], a0[3], bb.x, bb.y);
                    MMA16(c[2 * q + 1], a0[0], a0[1], a0[2], a0[3], bb.z, bb.w);
                }
            }
        }
    }

    // ---------------- 4 epilogues + 3 inner layers ----------------
#pragma unroll 1
    for (int l = 0; l < 4; l++) {
        const float* bias  = (l == 0) ? b0v  : bv  + (l - 1) * 128;
        const float* gamma = (l == 0) ? g0v  : gv  + (l - 1) * 128;
        const float* beta  = (l == 0) ? be0v : bev + (l - 1) * 128;

        float s0 = 0.f, q0 = 0.f, s1 = 0.f, q1 = 0.f;
#pragma unroll
        for (int j = 0; j < 16; j++) {
            int col = j * 8 + 2 * t4;
            float2 bb = __ldg((const float2*)(bias + col));
            c[j][0] += bb.x; c[j][1] += bb.y;
            c[j][2] += bb.x; c[j][3] += bb.y;
            s0 += c[j][0] + c[j][1];
            q0 += c[j][0] * c[j][0] + c[j][1] * c[j][1];
            s1 += c[j][2] + c[j][3];
            q1 += c[j][2] * c[j][2] + c[j][3] * c[j][3];
        }
#pragma unroll
        for (int o = 1; o <= 2; o <<= 1) {
            s0 += __shfl_xor_sync(0xFFFFFFFFu, s0, o);
            q0 += __shfl_xor_sync(0xFFFFFFFFu, q0, o);
            s1 += __shfl_xor_sync(0xFFFFFFFFu, s1, o);
            q1 += __shfl_xor_sync(0xFFFFFFFFu, q1, o);
        }
        float mean0 = s0 * (1.f / 128.f);
        float rstd0 = rsqrtf(q0 * (1.f / 128.f) - mean0 * mean0 + 1e-5f);
        float mean1 = s1 * (1.f / 128.f);
        float rstd1 = rsqrtf(q1 * (1.f / 128.f) - mean1 * mean1 + 1e-5f);

        if (l == 3) {
            int ra = row0 + g;
            int rb = ra + 8;
#pragma unroll
            for (int j = 0; j < 16; j++) {
                int col = j * 8 + 2 * t4;
                float2 gg = __ldg((const float2*)(gamma + col));
                float2 ee = __ldg((const float2*)(beta + col));
                if (ra < NN) {
                    float2 o1;
                    o1.x = fast_tanh((c[j][0] - mean0) * rstd0 * gg.x + ee.x);
                    o1.y = fast_tanh((c[j][1] - mean0) * rstd0 * gg.y + ee.y);
                    *(float2*)(out + (size_t)ra * DD + col) = o1;
                }
                if (rb < NN) {
                    float2 o2;
                    o2.x = fast_tanh((c[j][2] - mean1) * rstd1 * gg.x + ee.x);
                    o2.y = fast_tanh((c[j][3] - mean1) * rstd1 * gg.y + ee.y);
                    *(float2*)(out + (size_t)rb * DD + col) = o2;
                }
            }
            break;
        }

        // Write h (half2) into per-warp smem slab.
        __syncwarp();
#pragma unroll
        for (int j = 0; j < 16; j++) {
            int col = j * 8 + 2 * t4;
            float2 gg = __ldg((const float2*)(gamma + col));
            float2 ee = __ldg((const float2*)(beta + col));
            int ci = j * 4 + t4;
            float h00 = fast_tanh((c[j][0] - mean0) * rstd0 * gg.x + ee.x);
            float h01 = fast_tanh((c[j][1] - mean0) * rstd0 * gg.y + ee.y);
            float h10 = fast_tanh((c[j][2] - mean1) * rstd1 * gg.x + ee.x);
            float h11 = fast_tanh((c[j][3] - mean1) * rstd1 * gg.y + ee.y);
            Hw[(g) * HS16 + ci]     = pack_h2(h00, h01);
            Hw[(g + 8) * HS16 + ci] = pack_h2(h10, h11);
            c[j][0] = 0.f; c[j][1] = 0.f;
            c[j][2] = 0.f; c[j][3] = 0.f;
        }
        __syncwarp();

        // Next layer GEMM: h (in Hw) @ W[l], K = 128
#pragma unroll
        for (int kc = 0; kc < 4; kc++) {
            int chunk = 12 + l * 4 + kc;
#pragma unroll
            for (int s = 0; s < 2; s++) {
                int kidx = kc * 16 + s * 8 + t4;
                uint32_t a0[4];
                a0[0] = Hw[(g) * HS16 + kidx];
                a0[1] = Hw[(g + 8) * HS16 + kidx];
                a0[2] = Hw[(g) * HS16 + kidx + 4];
                a0[3] = Hw[(g + 8) * HS16 + kidx + 4];
                const uint4* wfk = WF + ((size_t)(chunk * 2 + s) << 8);
#pragma unroll
                for (int q = 0; q < 8; q++) {
                    uint4 bb = __ldg(&wfk[(q << 5) + lane]);
                    MMA16(c[2 * q],     a0[0], a0[1], a0[2], a0[3], bb.x, bb.y);
                    MMA16(c[2 * q + 1], a0[0], a0[1], a0[2], a0[3], bb.z, bb.w);
                }
            }
        }
    }
}

// ---------------------------------------------------------------------------
extern "C" void kernel_launch(void* const* d_in, const int* in_sizes, int n_in,
                              void* d_out, int out_size) {
    const float* x   = (const float*)d_in[0];
    const float* e   = (const float*)d_in[1];
    const int*   ei  = (const int*)d_in[2];
    const float* W0  = (const float*)d_in[3];
    const float* b0  = (const float*)d_in[4];
    const float* g0  = (const float*)d_in[5];
    const float* be0 = (const float*)d_in[6];
    const float* W   = (const float*)d_in[7];
    const float* b   = (const float*)d_in[8];
    const float* g   = (const float*)d_in[9];
    const float* be  = (const float*)d_in[10];
    float* out = (float*)d_out;

    uint32_t *xh, *mih, *moh;
    int *cnt, *offin, *offout, *curin, *curout;
    int2 *lin, *lout;
    uint4* wf;
    cudaGetSymbolAddress((void**)&xh, g_xh);
    cudaGetSymbolAddress((void**)&mih, g_mih);
    cudaGetSymbolAddress((void**)&moh, g_moh);
    cudaGetSymbolAddress((void**)&cnt, g_cnt);
    cudaGetSymbolAddress((void**)&offin, g_off_in);
    cudaGetSymbolAddress((void**)&offout, g_off_out);
    cudaGetSymbolAddress((void**)&curin, g_cur_in);
    cudaGetSymbolAddress((void**)&curout, g_cur_out);
    cudaGetSymbolAddress((void**)&lin, g_lst_in);
    cudaGetSymbolAddress((void**)&lout, g_lst_out);
    cudaGetSymbolAddress((void**)&wf, g_wfrag);
    int* cursors = cnt + 2 * NN;

    const int smem_bytes = 8 * 16 * HS16 * 4;   // 8 warps x 16 rows x 68 words
    cudaFuncSetAttribute(mlp_fused,
                         cudaFuncAttributeMaxDynamicSharedMemorySize,
                         smem_bytes);

    cudaMemsetAsync(cnt, 0, (2 * NN + 2) * sizeof(int));

    prep_kernel<<<PREP_BLOCKS, 256>>>(x, xh, W0, W, wf, ei, cnt);
    alloc_kernel<<<(2 * NN + 255) / 256, 256>>>(cnt, offin, curin, offout, curout, cursors);
    fill_kernel<<<(NE / 16 + 255) / 256, 256>>>(ei, e, curin, curout, lin, lout);

    {
        long long warps = 2LL * NN;
        int blocks = (int)((warps * 32 + 255) / 256);
        gather_kernel<<<blocks, 256>>>(xh, cnt, offin, lin, offout, lout, mih, moh);
    }

    const int gblocks = (NN + ROWS_PER_BLOCK - 1) / ROWS_PER_BLOCK;  // 782
    mlp_fused<<<gblocks, MLP_THREADS, smem_bytes>>>(
        mih, moh, xh, wf, b0, g0, be0, b, g, be, out);
}

// round 16
// speedup vs baseline: 1.3884x; 1.0645x over previous
#include <cuda_runtime.h>
#include <cuda_fp16.h>
#include <math.h>
#include <stdint.h>

#define NN 100000
#define DD 128
#define NE 1600000

#define MLP_THREADS 256          // 8 warps; each warp owns 16 rows
#define ROWS_PER_BLOCK 128
#define N_CHUNKS 24              // 12 layer-0 (384 k) + 12 inner (3 x 128 k)
#define HS16 68                  // H slab row stride in uint32 (half2) units
#define BUCKET 64                // fixed per-node edge-bucket capacity

// prep_kernel block ranges: fill first (latency-bound, start early),
// then xconv / wfrag (bandwidth-bound, overlap the fill atomics).
#define PREP_FILL_BLOCKS  782    // ceil(NE/8/256)
#define PREP_XCONV_BLOCKS 12500  // NN*128/4 float4s / 256 threads
#define PREP_WFRAG_BLOCKS 48     // N_CHUNKS*512/256
#define PREP_BLOCKS (PREP_FILL_BLOCKS + PREP_XCONV_BLOCKS + PREP_WFRAG_BLOCKS)

// Scratch (allocation-free rule: __device__ globals)
__device__ uint32_t g_xh[(size_t)NN * 64];    // x as half2 pairs (plain layout)
__device__ uint32_t g_mih[(size_t)NN * 64];
__device__ uint32_t g_moh[(size_t)NN * 64];

__device__ int   g_cnt[2 * NN];               // per-(node,dir) degree/cursor
__device__ int2  g_lst_in[(size_t)NN * BUCKET];    // {src, w-bits} bucket per dst
__device__ int2  g_lst_out[(size_t)NN * BUCKET];   // {dst, w-bits} bucket per src
__device__ uint4 g_wfrag[N_CHUNKS * 2 * 8 * 32];   // fp16 frag-major weights

// ---------------------------------------------------------------------------
__device__ __forceinline__ float fast_tanh(float x) {
    float ax = fabsf(x);
    float t = __expf(-2.f * ax);
    float r = (1.f - t) * __frcp_rn(1.f + t);
    return copysignf(r, x);
}

__device__ __forceinline__ uint32_t pack_h2(float a, float b) {
    __half2 h = __floats2half2_rn(a, b);
    return *(uint32_t*)&h;
}

// ---------------------------------------------------------------------------
// Fused prep: direct-bucket fill (blocks [0,782)), xconv (next 12500),
// wfrag (last 48). Fill needs no precomputed offsets: slot via atomicAdd.
// ---------------------------------------------------------------------------
__global__ void prep_kernel(const float* __restrict__ x, uint32_t* __restrict__ xh,
                            const float* __restrict__ W0, const float* __restrict__ W,
                            uint4* __restrict__ WF,
                            const int* __restrict__ ei, const float* __restrict__ e,
                            int* __restrict__ cnt,
                            int2* __restrict__ lin, int2* __restrict__ lout) {
    int b = blockIdx.x;
    if (b < PREP_FILL_BLOCKS) {
        // Direct bucket fill: 8 edges/thread
        int i = b * 256 + threadIdx.x;
        if (i >= NE / 8) return;
        int4 s0 = __ldg((const int4*)ei + 2 * i);
        int4 s1 = __ldg((const int4*)ei + 2 * i + 1);
        int4 t0 = __ldg((const int4*)(ei + NE) + 2 * i);
        int4 t1 = __ldg((const int4*)(ei + NE) + 2 * i + 1);
        float4 w0 = __ldg((const float4*)e + 2 * i);
        float4 w1 = __ldg((const float4*)e + 2 * i + 1);
        int ss[8] = {s0.x, s0.y, s0.z, s0.w, s1.x, s1.y, s1.z, s1.w};
        int tt[8] = {t0.x, t0.y, t0.z, t0.w, t1.x, t1.y, t1.z, t1.w};
        float ww[8] = {w0.x, w0.y, w0.z, w0.w, w1.x, w1.y, w1.z, w1.w};
        int pin[8], pout[8];
#pragma unroll
        for (int u = 0; u < 8; u++) pin[u] = atomicAdd(&cnt[tt[u]], 1);
#pragma unroll
        for (int u = 0; u < 8; u++) pout[u] = atomicAdd(&cnt[NN + ss[u]], 1);
#pragma unroll
        for (int u = 0; u < 8; u++)
            lin[(size_t)tt[u] * BUCKET + pin[u]] = make_int2(ss[u], __float_as_int(ww[u]));
#pragma unroll
        for (int u = 0; u < 8; u++)
            lout[(size_t)ss[u] * BUCKET + pout[u]] = make_int2(tt[u], __float_as_int(ww[u]));
        return;
    }
    b -= PREP_FILL_BLOCKS;
    if (b < PREP_XCONV_BLOCKS) {
        int i = b * 256 + threadIdx.x;
        float4 v = __ldg((const float4*)x + i);
        uint2 o;
        o.x = pack_h2(v.x, v.y);
        o.y = pack_h2(v.z, v.w);
        ((uint2*)xh)[i] = o;
        return;
    }
    b -= PREP_XCONV_BLOCKS;
    {
        int idx = b * 256 + threadIdx.x;
        int lane = idx & 31;
        int q = (idx >> 5) & 7;
        int s = (idx >> 8) & 1;
        int chunk = idx >> 9;
        int t4 = lane & 3, g = lane >> 2;

        const float* Wsrc;
        int kbase;
        if (chunk < 12) {
            Wsrc = W0;
            kbase = chunk * 32;
        } else {
            int c2 = chunk - 12;
            Wsrc = W + (size_t)(c2 >> 2) * 128 * 128;
            kbase = (c2 & 3) * 32;
        }
        int k0 = kbase + s * 16 + 2 * t4;
        int n0 = (2 * q) * 8 + g;
        int n1 = n0 + 8;

        uint4 o;
        o.x = pack_h2(__ldg(&Wsrc[(size_t)k0 * 128 + n0]),       __ldg(&Wsrc[(size_t)(k0 + 1) * 128 + n0]));
        o.y = pack_h2(__ldg(&Wsrc[(size_t)(k0 + 8) * 128 + n0]), __ldg(&Wsrc[(size_t)(k0 + 9) * 128 + n0]));
        o.z = pack_h2(__ldg(&Wsrc[(size_t)k0 * 128 + n1]),       __ldg(&Wsrc[(size_t)(k0 + 1) * 128 + n1]));
        o.w = pack_h2(__ldg(&Wsrc[(size_t)(k0 + 8) * 128 + n1]), __ldg(&Wsrc[(size_t)(k0 + 9) * 128 + n1]));
        WF[idx] = o;
    }
}

// ---------------------------------------------------------------------------
// Gather (fp16): one warp per (node, dir). Buckets at node*BUCKET.
// ---------------------------------------------------------------------------
__global__ __launch_bounds__(256) void gather_kernel(
    const uint32_t* __restrict__ xh, const int* __restrict__ cnt,
    const int2* __restrict__ lin, const int2* __restrict__ lout,
    uint32_t* __restrict__ mih, uint32_t* __restrict__ moh) {
    int wg = (blockIdx.x * blockDim.x + threadIdx.x) >> 5;
    int lane = threadIdx.x & 31;
    if (wg >= 2 * NN) return;

    const int2* lst;
    uint32_t* dst;
    int node;
    if (wg < NN) { node = wg; lst = lin; dst = mih; }
    else         { node = wg - NN; lst = lout; dst = moh; }

    int beg = node * BUCKET;
    int end = beg + cnt[wg];

    float2 acc0 = make_float2(0.f, 0.f);
    float2 acc1 = make_float2(0.f, 0.f);

    int j = beg;
    for (; j + 8 <= end; j += 8) {
        int2 p[8];
#pragma unroll
        for (int u = 0; u < 8; u++) p[u] = __ldg(&lst[j + u]);
        uint2 v[8];
#pragma unroll
        for (int u = 0; u < 8; u++)
            v[u] = __ldg((const uint2*)(xh + (size_t)p[u].x * 64) + lane);
#pragma unroll
        for (int u = 0; u < 8; u++) {
            float w = __int_as_float(p[u].y);
            float2 f0 = __half22float2(*(__half2*)&v[u].x);
            float2 f1 = __half22float2(*(__half2*)&v[u].y);
            acc0.x = fmaf(w, f0.x, acc0.x); acc0.y = fmaf(w, f0.y, acc0.y);
            acc1.x = fmaf(w, f1.x, acc1.x); acc1.y = fmaf(w, f1.y, acc1.y);
        }
    }
    for (; j < end; j++) {
        int2 p0 = __ldg(&lst[j]);
        uint2 v0 = __ldg((const uint2*)(xh + (size_t)p0.x * 64) + lane);
        float w = __int_as_float(p0.y);
        float2 f0 = __half22float2(*(__half2*)&v0.x);
        float2 f1 = __half22float2(*(__half2*)&v0.y);
        acc0.x = fmaf(w, f0.x, acc0.x); acc0.y = fmaf(w, f0.y, acc0.y);
        acc1.x = fmaf(w, f1.x, acc1.x); acc1.y = fmaf(w, f1.y, acc1.y);
    }

    uint2 o;
    o.x = pack_h2(acc0.x, acc0.y);
    o.y = pack_h2(acc1.x, acc1.y);
    ((uint2*)(dst + (size_t)node * 64))[lane] = o;
}

// ---------------------------------------------------------------------------
// Fused 4-layer MLP, fp16 m16n8k16. 16 rows per warp, 16 warps/SM.
// ---------------------------------------------------------------------------
#define MMA16(cj, A0r, A1r, A2r, A3r, B0r, B1r)                                  \
    asm volatile(                                                                \
        "mma.sync.aligned.m16n8k16.row.col.f32.f16.f16.f32 "                     \
        "{%0,%1,%2,%3}, {%4,%5,%6,%7}, {%8,%9}, {%0,%1,%2,%3};"                  \
        : "+f"(cj[0]), "+f"(cj[1]), "+f"(cj[2]), "+f"(cj[3])                     \
        : "r"(A0r), "r"(A1r), "r"(A2r), "r"(A3r), "r"(B0r), "r"(B1r))

__global__ __launch_bounds__(MLP_THREADS, 2) void mlp_fused(
    const uint32_t* __restrict__ A0h, const uint32_t* __restrict__ A1h,
    const uint32_t* __restrict__ A2h,
    const uint4* __restrict__ WF,
    const float* __restrict__ b0v, const float* __restrict__ g0v,
    const float* __restrict__ be0v,
    const float* __restrict__ bv, const float* __restrict__ gv,
    const float* __restrict__ bev,
    float* __restrict__ out)
{
    extern __shared__ uint32_t smem[];
    const int tid = threadIdx.x;
    const int lane = tid & 31;
    const int wid = tid >> 5;
    const int g = lane >> 2;
    const int t4 = lane & 3;
    const int row0 = blockIdx.x * ROWS_PER_BLOCK + wid * 16;

    uint32_t* Hw = smem + wid * 16 * HS16;   // per-warp slab [16][HS16] half2

    float c[16][4];
#pragma unroll
    for (int j = 0; j < 16; j++)
#pragma unroll
        for (int q = 0; q < 4; q++) c[j][q] = 0.f;

    int r00 = row0 + g;
    size_t cr00 = (size_t)(r00 < NN ? r00 : 0) * 64;
    size_t cr01 = (size_t)((r00 + 8) < NN ? (r00 + 8) : 0) * 64;

    // ---------------- Layer 0: K = 384 over {mih, moh, xh} ----------------
    const uint32_t* Ap[3] = {A0h, A1h, A2h};
#pragma unroll 1
    for (int m = 0; m < 3; m++) {
        const uint32_t* A = Ap[m];
#pragma unroll
        for (int kc = 0; kc < 4; kc++) {
            int chunk = m * 4 + kc;
#pragma unroll
            for (int s = 0; s < 2; s++) {
                int kidx = kc * 16 + s * 8 + t4;       // uint32 (half2) index
                uint32_t a0[4];
                a0[0] = __ldg(A + cr00 + kidx);
                a0[1] = __ldg(A + cr01 + kidx);
                a0[2] = __ldg(A + cr00 + kidx + 4);
                a0[3] = __ldg(A + cr01 + kidx + 4);
                const uint4* wfk = WF + ((size_t)(chunk * 2 + s) << 8);
#pragma unroll
                for (int q = 0; q < 8; q++) {
                    uint4 bb = __ldg(&wfk[(q << 5) + lane]);
                    MMA16(c[2 * q],     a0[0], a0[1], a0[2], a0[3], bb.x, bb.y);
                    MMA16(c[2 * q + 1], a0[0], a0[1], a0[2], a0[3], bb.z, bb.w);
                }
            }
        }
    }

    // ---------------- 4 epilogues + 3 inner layers ----------------
#pragma unroll 1
    for (int l = 0; l < 4; l++) {
        const float* bias  = (l == 0) ? b0v  : bv  + (l - 1) * 128;
        const float* gamma = (l == 0) ? g0v  : gv  + (l - 1) * 128;
        const float* beta  = (l == 0) ? be0v : bev + (l - 1) * 128;

        float s0 = 0.f, q0 = 0.f, s1 = 0.f, q1 = 0.f;
#pragma unroll
        for (int j = 0; j < 16; j++) {
            int col = j * 8 + 2 * t4;
            float2 bb = __ldg((const float2*)(bias + col));
            c[j][0] += bb.x; c[j][1] += bb.y;
            c[j][2] += bb.x; c[j][3] += bb.y;
            s0 += c[j][0] + c[j][1];
            q0 += c[j][0] * c[j][0] + c[j][1] * c[j][1];
            s1 += c[j][2] + c[j][3];
            q1 += c[j][2] * c[j][2] + c[j][3] * c[j][3];
        }
#pragma unroll
        for (int o = 1; o <= 2; o <<= 1) {
            s0 += __shfl_xor_sync(0xFFFFFFFFu, s0, o);
            q0 += __shfl_xor_sync(0xFFFFFFFFu, q0, o);
            s1 += __shfl_xor_sync(0xFFFFFFFFu, s1, o);
            q1 += __shfl_xor_sync(0xFFFFFFFFu, q1, o);
        }
        float mean0 = s0 * (1.f / 128.f);
        float rstd0 = rsqrtf(q0 * (1.f / 128.f) - mean0 * mean0 + 1e-5f);
        float mean1 = s1 * (1.f / 128.f);
        float rstd1 = rsqrtf(q1 * (1.f / 128.f) - mean1 * mean1 + 1e-5f);

        if (l == 3) {
            int ra = row0 + g;
            int rb = ra + 8;
#pragma unroll
            for (int j = 0; j < 16; j++) {
                int col = j * 8 + 2 * t4;
                float2 gg = __ldg((const float2*)(gamma + col));
                float2 ee = __ldg((const float2*)(beta + col));
                if (ra < NN) {
                    float2 o1;
                    o1.x = fast_tanh((c[j][0] - mean0) * rstd0 * gg.x + ee.x);
                    o1.y = fast_tanh((c[j][1] - mean0) * rstd0 * gg.y + ee.y);
                    *(float2*)(out + (size_t)ra * DD + col) = o1;
                }
                if (rb < NN) {
                    float2 o2;
                    o2.x = fast_tanh((c[j][2] - mean1) * rstd1 * gg.x + ee.x);
                    o2.y = fast_tanh((c[j][3] - mean1) * rstd1 * gg.y + ee.y);
                    *(float2*)(out + (size_t)rb * DD + col) = o2;
                }
            }
            break;
        }

        // Write h (half2) into per-warp smem slab.
        __syncwarp();
#pragma unroll
        for (int j = 0; j < 16; j++) {
            int col = j * 8 + 2 * t4;
            float2 gg = __ldg((const float2*)(gamma + col));
            float2 ee = __ldg((const float2*)(beta + col));
            int ci = j * 4 + t4;
            float h00 = fast_tanh((c[j][0] - mean0) * rstd0 * gg.x + ee.x);
            float h01 = fast_tanh((c[j][1] - mean0) * rstd0 * gg.y + ee.y);
            float h10 = fast_tanh((c[j][2] - mean1) * rstd1 * gg.x + ee.x);
            float h11 = fast_tanh((c[j][3] - mean1) * rstd1 * gg.y + ee.y);
            Hw[(g) * HS16 + ci]     = pack_h2(h00, h01);
            Hw[(g + 8) * HS16 + ci] = pack_h2(h10, h11);
            c[j][0] = 0.f; c[j][1] = 0.f;
            c[j][2] = 0.f; c[j][3] = 0.f;
        }
        __syncwarp();

        // Next layer GEMM: h (in Hw) @ W[l], K = 128
#pragma unroll
        for (int kc = 0; kc < 4; kc++) {
            int chunk = 12 + l * 4 + kc;
#pragma unroll
            for (int s = 0; s < 2; s++) {
                int kidx = kc * 16 + s * 8 + t4;
                uint32_t a0[4];
                a0[0] = Hw[(g) * HS16 + kidx];
                a0[1] = Hw[(g + 8) * HS16 + kidx];
                a0[2] = Hw[(g) * HS16 + kidx + 4];
                a0[3] = Hw[(g + 8) * HS16 + kidx + 4];
                const uint4* wfk = WF + ((size_t)(chunk * 2 + s) << 8);
#pragma unroll
                for (int q = 0; q < 8; q++) {
                    uint4 bb = __ldg(&wfk[(q << 5) + lane]);
                    MMA16(c[2 * q],     a0[0], a0[1], a0[2], a0[3], bb.x, bb.y);
                    MMA16(c[2 * q + 1], a0[0], a0[1], a0[2], a0[3], bb.z, bb.w);
                }
            }
        }
    }
}

// ---------------------------------------------------------------------------
extern "C" void kernel_launch(void* const* d_in, const int* in_sizes, int n_in,
                              void* d_out, int out_size) {
    const float* x   = (const float*)d_in[0];
    const float* e   = (const float*)d_in[1];
    const int*   ei  = (const int*)d_in[2];
    const float* W0  = (const float*)d_in[3];
    const float* b0  = (const float*)d_in[4];
    const float* g0  = (const float*)d_in[5];
    const float* be0 = (const float*)d_in[6];
    const float* W   = (const float*)d_in[7];
    const float* b   = (const float*)d_in[8];
    const float* g   = (const float*)d_in[9];
    const float* be  = (const float*)d_in[10];
    float* out = (float*)d_out;

    uint32_t *xh, *mih, *moh;
    int *cnt;
    int2 *lin, *lout;
    uint4* wf;
    cudaGetSymbolAddress((void**)&xh, g_xh);
    cudaGetSymbolAddress((void**)&mih, g_mih);
    cudaGetSymbolAddress((void**)&moh, g_moh);
    cudaGetSymbolAddress((void**)&cnt, g_cnt);
    cudaGetSymbolAddress((void**)&lin, g_lst_in);
    cudaGetSymbolAddress((void**)&lout, g_lst_out);
    cudaGetSymbolAddress((void**)&wf, g_wfrag);

    const int smem_bytes = 8 * 16 * HS16 * 4;   // 8 warps x 16 rows x 68 words
    cudaFuncSetAttribute(mlp_fused,
                         cudaFuncAttributeMaxDynamicSharedMemorySize,
                         smem_bytes);

    cudaMemsetAsync(cnt, 0, 2 * NN * sizeof(int));

    prep_kernel<<<PREP_BLOCKS, 256>>>(x, xh, W0, W, wf, ei, e, cnt, lin, lout);

    {
        long long warps = 2LL * NN;
        int blocks = (int)((warps * 32 + 255) / 256);
        gather_kernel<<<blocks, 256>>>(xh, cnt, lin, lout, mih, moh);
    }

    const int gblocks = (NN + ROWS_PER_BLOCK - 1) / ROWS_PER_BLOCK;  // 782
    mlp_fused<<<gblocks, MLP_THREADS, smem_bytes>>>(
        mih, moh, xh, wf, b0, g0, be0, b, g, be, out);
}